// round 12
// baseline (speedup 1.0000x reference)
#include <cuda_runtime.h>
#include <cuda_bf16.h>
#include <cuda_fp16.h>
#include <cstdint>

#define BATCH 64
#define CDIM  512
#define NTOK  1024
#define HB    32            // half-batch

typedef __nv_bfloat16 bf;

// ---------------- scratch (device globals) ----------------------------------
__device__ float g_WT [(size_t)512 * 1536];
__device__ float g_rhw[(size_t)64 * 512];
__device__ bf g_Mh[(size_t)512 * 512];
__device__ bf g_Mm[(size_t)512 * 512];
__device__ bf g_Gh[(size_t)64 * 512];
__device__ bf g_Gm[(size_t)64 * 512];
__device__ bf g_xTh[(size_t)BATCH * NTOK * CDIM];
__device__ bf g_xTm[(size_t)BATCH * NTOK * CDIM];
__device__ __half g_xT16[(size_t)BATCH * NTOK * CDIM];
__device__ __half g_W16h[(size_t)512 * 512];
__device__ bf g_Th[(size_t)BATCH * NTOK * 512];
__device__ bf g_Tm[(size_t)BATCH * NTOK * 512];
__device__ float  g_logit[(size_t)BATCH * NTOK * NTOK];
__device__ float  g_P[(size_t)BATCH * 64 * NTOK];
__device__ __half g_v16[(size_t)BATCH * CDIM * NTOK];
__device__ __half g_att16[(size_t)BATCH * NTOK * NTOK];

// ---------------- PTX helpers ----------------------------------------------
__device__ __forceinline__ uint32_t smem_u32(const void* p) {
    uint32_t a;
    asm("{ .reg .u64 t; cvta.to.shared.u64 t, %1; cvt.u32.u64 %0, t; }" : "=r"(a) : "l"(p));
    return a;
}
__device__ __forceinline__ void cpa16(uint32_t dst, const void* src) {
    asm volatile("cp.async.cg.shared.global [%0], [%1], 16;" :: "r"(dst), "l"(src));
}
__device__ __forceinline__ void ldsm4(uint32_t r[4], uint32_t addr) {
    asm volatile("ldmatrix.sync.aligned.m8n8.x4.shared.b16 {%0,%1,%2,%3}, [%4];"
                 : "=r"(r[0]), "=r"(r[1]), "=r"(r[2]), "=r"(r[3]) : "r"(addr));
}
__device__ __forceinline__ void mma16816(float c[4], const uint32_t a[4], const uint32_t b[2]) {
    asm volatile("mma.sync.aligned.m16n8k16.row.col.f32.bf16.bf16.f32 "
                 "{%0,%1,%2,%3}, {%4,%5,%6,%7}, {%8,%9}, {%0,%1,%2,%3};"
                 : "+f"(c[0]), "+f"(c[1]), "+f"(c[2]), "+f"(c[3])
                 : "r"(a[0]), "r"(a[1]), "r"(a[2]), "r"(a[3]), "r"(b[0]), "r"(b[1]));
}
__device__ __forceinline__ void mma16816h(float c[4], const uint32_t a[4], const uint32_t b[2]) {
    asm volatile("mma.sync.aligned.m16n8k16.row.col.f32.f16.f16.f32 "
                 "{%0,%1,%2,%3}, {%4,%5,%6,%7}, {%8,%9}, {%0,%1,%2,%3};"
                 : "+f"(c[0]), "+f"(c[1]), "+f"(c[2]), "+f"(c[3])
                 : "r"(a[0]), "r"(a[1]), "r"(a[2]), "r"(a[3]), "r"(b[0]), "r"(b[1]));
}
__device__ __forceinline__ uint32_t sw_off(int row, int chunk) {
    return (uint32_t)(row * 64 + ((chunk ^ ((row >> 1) & 3)) << 4));
}
__device__ __forceinline__ void split_store(bf* __restrict__ ph, bf* __restrict__ pm,
                                            size_t off, float v0, float v1) {
    bf h0 = __float2bfloat16(v0), h1 = __float2bfloat16(v1);
    bf m0 = __float2bfloat16(v0 - __bfloat162float(h0));
    bf m1 = __float2bfloat16(v1 - __bfloat162float(h1));
    __nv_bfloat162 hh; hh.x = h0; hh.y = h1;
    __nv_bfloat162 mm; mm.x = m0; mm.y = m1;
    *reinterpret_cast<__nv_bfloat162*>(ph + off) = hh;
    *reinterpret_cast<__nv_bfloat162*>(pm + off) = mm;
}

// ================= 3-term bf16 GEMM, 128x128 tile, 4 warps ==================
#define OFF_AH 0
#define OFF_AM 8192
#define OFF_BH 16384
#define OFF_BM 24576
#define STAGE_BYTES 32768
#define NSTAGE 3
#define SMEM_MAIN (NSTAGE * STAGE_BYTES)

template <int MODE>
__global__ __launch_bounds__(128, 2) void gemm3(int b0) {
    extern __shared__ __align__(128) char smem[];
    const uint32_t sbase = smem_u32(smem);
    const int tid = threadIdx.x;
    const int wid = tid >> 5, lane = tid & 31;
    const int b = blockIdx.z + b0;
    const int nBase = blockIdx.x * 128;
    const int mBase = blockIdx.y * 128;
    const int wm = (wid >> 1) * 64, wn = (wid & 1) * 64;

    constexpr int NIT = 16;
    const size_t bXT = (size_t)b << 19;
    const size_t bQK = (size_t)b << 20;

    float acc[4][8][4];
#pragma unroll
    for (int i = 0; i < 4; i++)
#pragma unroll
        for (int j = 0; j < 8; j++)
#pragma unroll
            for (int k = 0; k < 4; k++) acc[i][j][k] = 0.f;

    auto issue_stage = [&](int stage, int kt) {
        const bf *pah, *pam, *pbh, *pbm;
        pah = g_xTh + bXT + (size_t)mBase * 512 + kt;
        pam = g_xTm + bXT + (size_t)mBase * 512 + kt;
        if (MODE == 0) {
            pbh = g_Mh + (size_t)nBase * 512 + kt;
            pbm = g_Mm + (size_t)nBase * 512 + kt;
        } else {
            pbh = g_Th + bXT + (size_t)nBase * 512 + kt;
            pbm = g_Tm + bXT + (size_t)nBase * 512 + kt;
        }
        const uint32_t sb = sbase + stage * STAGE_BYTES;
#pragma unroll
        for (int j = 0; j < 4; j++) {
            const int idx = tid + j * 128;
            const int row = idx >> 2, ch = idx & 3;
            const uint32_t d = sw_off(row, ch);
            const int s = row * 512 + ch * 8;
            cpa16(sb + OFF_AH + d, pah + s);
            cpa16(sb + OFF_AM + d, pam + s);
            cpa16(sb + OFF_BH + d, pbh + s);
            cpa16(sb + OFF_BM + d, pbm + s);
        }
        asm volatile("cp.async.commit_group;");
    };

    auto compute = [&](int stage) {
        const uint32_t base = sbase + stage * STAGE_BYTES;
        const int sel = lane >> 3;
#pragma unroll
        for (int k8 = 0; k8 < 2; k8++) {
            uint32_t bhf[8][2], bmf[8][2];
#pragma unroll
            for (int pr = 0; pr < 4; pr++) {
                const int nt = 2 * pr + (sel >> 1);
                const int kb = sel & 1;
                const uint32_t ra = base + OFF_BH + sw_off(wn + nt * 8 + (lane & 7), k8 * 2 + kb);
                uint32_t r[4];
                ldsm4(r, ra);
                bhf[2 * pr][0] = r[0]; bhf[2 * pr][1] = r[1];
                bhf[2 * pr + 1][0] = r[2]; bhf[2 * pr + 1][1] = r[3];
                ldsm4(r, ra + (OFF_BM - OFF_BH));
                bmf[2 * pr][0] = r[0]; bmf[2 * pr][1] = r[1];
                bmf[2 * pr + 1][0] = r[2]; bmf[2 * pr + 1][1] = r[3];
            }
#pragma unroll
            for (int mt = 0; mt < 4; mt++) {
                const uint32_t aa = base + OFF_AH +
                    sw_off(wm + mt * 16 + (sel & 1) * 8 + (lane & 7), k8 * 2 + (sel >> 1));
                uint32_t ah[4], am[4];
                ldsm4(ah, aa);
                ldsm4(am, aa + (OFF_AM - OFF_AH));
#pragma unroll
                for (int nt = 0; nt < 8; nt++) mma16816(acc[mt][nt], ah, bhf[nt]);
#pragma unroll
                for (int nt = 0; nt < 8; nt++) mma16816(acc[mt][nt], ah, bmf[nt]);
#pragma unroll
                for (int nt = 0; nt < 8; nt++) mma16816(acc[mt][nt], am, bhf[nt]);
            }
        }
    };

    issue_stage(0, 0);
    issue_stage(1, 32);
    for (int it = 0; it < NIT; it++) {
        if (it + 2 < NIT) asm volatile("cp.async.wait_group 1;");
        else              asm volatile("cp.async.wait_group 0;");
        __syncthreads();
        if (it + 2 < NIT) issue_stage((it + 2) % NSTAGE, (it + 2) * 32);
        compute(it % NSTAGE);
    }

    const int lr = lane >> 2, lc = 2 * (lane & 3);
#pragma unroll
    for (int mt = 0; mt < 4; mt++) {
#pragma unroll
        for (int nt = 0; nt < 8; nt++) {
            const int r0 = mBase + wm + mt * 16 + lr;
            const int c0 = nBase + wn + nt * 8 + lc;
            if (MODE == 0) {
                split_store(g_Th + bXT, g_Tm + bXT, (size_t)r0 * 512 + c0, acc[mt][nt][0], acc[mt][nt][1]);
                split_store(g_Th + bXT, g_Tm + bXT, (size_t)(r0 + 8) * 512 + c0, acc[mt][nt][2], acc[mt][nt][3]);
            } else {
                float2 v0; v0.x = acc[mt][nt][0]; v0.y = acc[mt][nt][1];
                float2 v1; v1.x = acc[mt][nt][2]; v1.y = acc[mt][nt][3];
                *reinterpret_cast<float2*>(g_logit + bQK + (size_t)r0 * 1024 + c0) = v0;
                *reinterpret_cast<float2*>(g_logit + bQK + (size_t)(r0 + 8) * 1024 + c0) = v1;
            }
        }
    }
}

// ================= P GEMM: P[b][r][m] = G[r][:] . xT[m][:] ==================
#define P_AH 0
#define P_AM 4096
#define P_BH 8192
#define P_BM 16384
#define P_STAGE 24576
#define SMEM_P (NSTAGE * P_STAGE)

__global__ __launch_bounds__(256, 2) void p_gemm(int b0) {
    extern __shared__ __align__(128) char smem[];
    const uint32_t sbase = smem_u32(smem);
    const int tid = threadIdx.x;
    const int wid = tid >> 5, lane = tid & 31;
    const int b = blockIdx.z + b0;
    const int nBase = blockIdx.x * 128;
    const int wm = (wid >> 2) * 32, wn = (wid & 3) * 32;
    const size_t bXT = (size_t)b << 19;

    float acc[2][4][4];
#pragma unroll
    for (int i = 0; i < 2; i++)
#pragma unroll
        for (int j = 0; j < 4; j++)
#pragma unroll
            for (int k = 0; k < 4; k++) acc[i][j][k] = 0.f;

    auto issue_stage = [&](int stage, int kt) {
        const uint32_t sb = sbase + stage * P_STAGE;
        {
            const int row = tid >> 2, ch = tid & 3;
            const uint32_t d = sw_off(row, ch);
            const int s = row * 512 + kt + ch * 8;
            cpa16(sb + P_AH + d, g_Gh + s);
            cpa16(sb + P_AM + d, g_Gm + s);
        }
#pragma unroll
        for (int j = 0; j < 2; j++) {
            const int idx = tid + j * 256;
            const int row = idx >> 2, ch = idx & 3;
            const uint32_t d = sw_off(row, ch);
            const size_t s = bXT + (size_t)(nBase + row) * 512 + kt + ch * 8;
            cpa16(sb + P_BH + d, g_xTh + s);
            cpa16(sb + P_BM + d, g_xTm + s);
        }
        asm volatile("cp.async.commit_group;");
    };

    auto compute = [&](int stage) {
        const uint32_t base = sbase + stage * P_STAGE;
        const int sel = lane >> 3;
#pragma unroll
        for (int k8 = 0; k8 < 2; k8++) {
            uint32_t bhf[4][2], bmf[4][2];
#pragma unroll
            for (int pr = 0; pr < 2; pr++) {
                const int nt = 2 * pr + (sel >> 1);
                const int kb = sel & 1;
                const uint32_t ra = base + P_BH + sw_off(wn + nt * 8 + (lane & 7), k8 * 2 + kb);
                uint32_t r[4];
                ldsm4(r, ra);
                bhf[2 * pr][0] = r[0]; bhf[2 * pr][1] = r[1];
                bhf[2 * pr + 1][0] = r[2]; bhf[2 * pr + 1][1] = r[3];
                ldsm4(r, ra + (P_BM - P_BH));
                bmf[2 * pr][0] = r[0]; bmf[2 * pr][1] = r[1];
                bmf[2 * pr + 1][0] = r[2]; bmf[2 * pr + 1][1] = r[3];
            }
#pragma unroll
            for (int mt = 0; mt < 2; mt++) {
                const uint32_t aa = base + P_AH +
                    sw_off(wm + mt * 16 + (sel & 1) * 8 + (lane & 7), k8 * 2 + (sel >> 1));
                uint32_t ah[4], am[4];
                ldsm4(ah, aa);
                ldsm4(am, aa + (P_AM - P_AH));
#pragma unroll
                for (int nt = 0; nt < 4; nt++) mma16816(acc[mt][nt], ah, bhf[nt]);
#pragma unroll
                for (int nt = 0; nt < 4; nt++) mma16816(acc[mt][nt], ah, bmf[nt]);
#pragma unroll
                for (int nt = 0; nt < 4; nt++) mma16816(acc[mt][nt], am, bhf[nt]);
            }
        }
    };

    issue_stage(0, 0);
    issue_stage(1, 32);
    for (int it = 0; it < 16; it++) {
        if (it + 2 < 16) asm volatile("cp.async.wait_group 1;");
        else             asm volatile("cp.async.wait_group 0;");
        __syncthreads();
        if (it + 2 < 16) issue_stage((it + 2) % NSTAGE, (it + 2) * 32);
        compute(it % NSTAGE);
    }

    const int lr = lane >> 2, lc = 2 * (lane & 3);
    float* P = g_P + (size_t)b * 64 * 1024;
#pragma unroll
    for (int mt = 0; mt < 2; mt++) {
#pragma unroll
        for (int nt = 0; nt < 4; nt++) {
            const int r0 = wm + mt * 16 + lr;
            const int c0 = nBase + wn + nt * 8 + lc;
            float2 v0; v0.x = acc[mt][nt][0]; v0.y = acc[mt][nt][1];
            float2 v1; v1.x = acc[mt][nt][2]; v1.y = acc[mt][nt][3];
            *reinterpret_cast<float2*>(P + (size_t)r0 * 1024 + c0) = v0;
            *reinterpret_cast<float2*>(P + (size_t)(r0 + 8) * 1024 + c0) = v1;
        }
    }
}

// ======= fp16 single-term GEMM: 128x128 tile, 4 warps =======================
#define U_A  0
#define U_B  8192
#define U_STAGE 16384
#define SMEM_U (NSTAGE * U_STAGE)

template <int MODE>
__global__ __launch_bounds__(128, 2) void h1_gemm(float* __restrict__ outp, int b0) {
    extern __shared__ __align__(128) char smem[];
    const uint32_t sbase = smem_u32(smem);
    const int tid = threadIdx.x;
    const int wid = tid >> 5, lane = tid & 31;
    const int b = blockIdx.z + b0;
    const int nBase = blockIdx.x * 128;
    const int mBase = blockIdx.y * 128;
    const int wm = (wid >> 1) * 64, wn = (wid & 1) * 64;
    const size_t bQK = (size_t)b << 20;
    const size_t bXT = (size_t)b << 19;

    constexpr int NIT = (MODE == 0) ? 16 : 32;
    constexpr int LD  = (MODE == 0) ? 512 : 1024;

    float acc[4][8][4];
#pragma unroll
    for (int i = 0; i < 4; i++)
#pragma unroll
        for (int j = 0; j < 8; j++)
#pragma unroll
            for (int k = 0; k < 4; k++) acc[i][j][k] = 0.f;

    auto issue_stage = [&](int stage, int kt) {
        const __half *pa, *pb;
        if (MODE == 0) {
            pa = g_W16h + (size_t)mBase * 512 + kt;
            pb = g_xT16 + bXT + (size_t)nBase * 512 + kt;
        } else {
            pa = g_v16 + bXT + (size_t)mBase * 1024 + kt;
            pb = g_att16 + bQK + (size_t)nBase * 1024 + kt;
        }
        const uint32_t sb = sbase + stage * U_STAGE;
#pragma unroll
        for (int j = 0; j < 4; j++) {
            const int idx = tid + j * 128;
            const int row = idx >> 2, ch = idx & 3;
            const uint32_t d = sw_off(row, ch);
            const int s = row * LD + ch * 8;
            cpa16(sb + U_A + d, pa + s);
            cpa16(sb + U_B + d, pb + s);
        }
        asm volatile("cp.async.commit_group;");
    };

    auto compute = [&](int stage) {
        const uint32_t base = sbase + stage * U_STAGE;
        const int sel = lane >> 3;
#pragma unroll
        for (int k8 = 0; k8 < 2; k8++) {
            uint32_t bff[8][2];
#pragma unroll
            for (int pr = 0; pr < 4; pr++) {
                const int nt = 2 * pr + (sel >> 1);
                const int kb = sel & 1;
                uint32_t r[4];
                ldsm4(r, base + U_B + sw_off(wn + nt * 8 + (lane & 7), k8 * 2 + kb));
                bff[2 * pr][0] = r[0]; bff[2 * pr][1] = r[1];
                bff[2 * pr + 1][0] = r[2]; bff[2 * pr + 1][1] = r[3];
            }
#pragma unroll
            for (int mt = 0; mt < 4; mt++) {
                const uint32_t aa = base + U_A +
                    sw_off(wm + mt * 16 + (sel & 1) * 8 + (lane & 7), k8 * 2 + (sel >> 1));
                uint32_t ah[4];
                ldsm4(ah, aa);
#pragma unroll
                for (int nt = 0; nt < 8; nt++) mma16816h(acc[mt][nt], ah, bff[nt]);
            }
        }
    };

    issue_stage(0, 0);
    issue_stage(1, 32);
    for (int it = 0; it < NIT; it++) {
        if (it + 2 < NIT) asm volatile("cp.async.wait_group 1;");
        else              asm volatile("cp.async.wait_group 0;");
        __syncthreads();
        if (it + 2 < NIT) issue_stage((it + 2) % NSTAGE, (it + 2) * 32);
        compute(it % NSTAGE);
    }

    const int lr = lane >> 2, lc = 2 * (lane & 3);
#pragma unroll
    for (int mt = 0; mt < 4; mt++) {
#pragma unroll
        for (int nt = 0; nt < 8; nt++) {
            const int r0 = mBase + wm + mt * 16 + lr;
            const int c0 = nBase + wn + nt * 8 + lc;
            if (MODE == 0) {
                __half* ov = g_v16 + bXT;
                __half2 h0; h0.x = __float2half_rn(acc[mt][nt][0]); h0.y = __float2half_rn(acc[mt][nt][1]);
                __half2 h1; h1.x = __float2half_rn(acc[mt][nt][2]); h1.y = __float2half_rn(acc[mt][nt][3]);
                *reinterpret_cast<__half2*>(ov + (size_t)r0 * 1024 + c0) = h0;
                *reinterpret_cast<__half2*>(ov + (size_t)(r0 + 8) * 1024 + c0) = h1;
            } else {
                float* of = outp + bXT;
                float2 v0; v0.x = acc[mt][nt][0]; v0.y = acc[mt][nt][1];
                float2 v1; v1.x = acc[mt][nt][2]; v1.y = acc[mt][nt][3];
                *reinterpret_cast<float2*>(of + (size_t)r0 * 1024 + c0) = v0;
                *reinterpret_cast<float2*>(of + (size_t)(r0 + 8) * 1024 + c0) = v1;
            }
        }
    }
}

// ---------------- small fp32 GEMM for M and G precompute --------------------
template <int IS_G>
__global__ __launch_bounds__(256) void sgemm_split() {
    const float* A = IS_G ? g_rhw : g_WT;
    const int lda = IS_G ? 512 : 1536;
    const float* B = IS_G ? g_WT : (g_WT + 512);
    const int ldb = 1536;
    bf* Ch = IS_G ? g_Gh : g_Mh;
    bf* Cm = IS_G ? g_Gm : g_Mm;

    __shared__ float As[16][72];
    __shared__ float Bs[16][72];
    const int tid = threadIdx.x;
    const int tx = tid & 15, ty = tid >> 4;
    const int rBase = blockIdx.y * 64, cBase = blockIdx.x * 64;

    float acc[4][4];
#pragma unroll
    for (int i = 0; i < 4; i++)
#pragma unroll
        for (int j = 0; j < 4; j++) acc[i][j] = 0.f;

    for (int kt = 0; kt < 512; kt += 16) {
        const int row = tid >> 2, q = (tid & 3) * 4;
        float4 va = *(const float4*)&A[(size_t)(rBase + row) * lda + kt + q];
        As[q + 0][row] = va.x; As[q + 1][row] = va.y;
        As[q + 2][row] = va.z; As[q + 3][row] = va.w;
        float4 vb = *(const float4*)&B[(size_t)(cBase + row) * ldb + kt + q];
        Bs[q + 0][row] = vb.x; Bs[q + 1][row] = vb.y;
        Bs[q + 2][row] = vb.z; Bs[q + 3][row] = vb.w;
        __syncthreads();
#pragma unroll
        for (int k = 0; k < 16; k++) {
            float a[4], bb[4];
            *(float4*)&a[0]  = *(const float4*)&As[k][ty * 4];
            *(float4*)&bb[0] = *(const float4*)&Bs[k][tx * 4];
#pragma unroll
            for (int i = 0; i < 4; i++)
#pragma unroll
                for (int j = 0; j < 4; j++) acc[i][j] += a[i] * bb[j];
        }
        __syncthreads();
    }
#pragma unroll
    for (int i = 0; i < 4; i++) {
        const int row = rBase + ty * 4 + i;
        const int col = cBase + tx * 4;
        split_store(Ch, Cm, (size_t)row * 512 + col, acc[i][0], acc[i][1]);
        split_store(Ch, Cm, (size_t)row * 512 + col + 2, acc[i][2], acc[i][3]);
    }
}

// ---------------- prep kernels ----------------------------------------------
__global__ void transpose_w(const float* __restrict__ W) {
    __shared__ float t[32][33];
    int o0 = blockIdx.x * 32, c0 = blockIdx.y * 32;
    int tx = threadIdx.x, ty = threadIdx.y;
#pragma unroll
    for (int j = 0; j < 32; j += 8)
        t[ty + j][tx] = W[(size_t)(o0 + ty + j) * 512 + c0 + tx];
    __syncthreads();
#pragma unroll
    for (int j = 0; j < 32; j += 8)
        g_WT[(size_t)(c0 + ty + j) * 1536 + o0 + tx] = t[tx][ty + j];
}

__global__ void prep_rhw(const float* __restrict__ rel_h, const float* __restrict__ rel_w) {
    int idx = blockIdx.x * blockDim.x + threadIdx.x;
    if (idx >= 64 * 512) return;
    int r = idx >> 9, c = idx & 511;
    g_rhw[idx] = (r < 32) ? rel_h[c * 32 + r] : rel_w[c * 32 + (r - 32)];
}

__global__ void prep_w16(const float* __restrict__ W) {
    int idx = blockIdx.x * blockDim.x + threadIdx.x;
    if (idx >= 512 * 512) return;
    int cv = idx >> 9, c = idx & 511;
    g_W16h[idx] = __float2half_rn(W[(size_t)(1024 + cv) * 512 + c]);
}

__global__ void transpose_x(const float* __restrict__ x, int b0) {
    __shared__ float t[64][33];
    int b = blockIdx.z + b0;
    int n0 = blockIdx.x * 32, c0 = blockIdx.y * 64;
    const float* src = x + (size_t)b * CDIM * NTOK;
    size_t dbase = (size_t)b * NTOK * CDIM;
    int tx = threadIdx.x, ty = threadIdx.y;
#pragma unroll
    for (int j = 0; j < 8; j++)
        t[ty + j * 8][tx] = src[(size_t)(c0 + ty + j * 8) * NTOK + n0 + tx];
    __syncthreads();
#pragma unroll
    for (int j = 0; j < 4; j++) {
        int n = ty + j * 8;
        float v0 = t[2 * tx][n], v1 = t[2 * tx + 1][n];
        size_t off = dbase + (size_t)(n0 + n) * CDIM + c0 + 2 * tx;
        bf h0 = __float2bfloat16(v0), h1 = __float2bfloat16(v1);
        __nv_bfloat162 hh; hh.x = h0; hh.y = h1;
        __nv_bfloat162 mm;
        mm.x = __float2bfloat16(v0 - __bfloat162float(h0));
        mm.y = __float2bfloat16(v1 - __bfloat162float(h1));
        __half2 xx; xx.x = __float2half_rn(v0); xx.y = __float2half_rn(v1);
        *reinterpret_cast<__nv_bfloat162*>(g_xTh + off) = hh;
        *reinterpret_cast<__nv_bfloat162*>(g_xTm + off) = mm;
        *reinterpret_cast<__half2*>(g_xT16 + off) = xx;
    }
}

// softmax over m with fused pos-bias; writes fp16 att
__global__ __launch_bounds__(256) void softmax_bias(int b0) {
    size_t row = blockIdx.x + (size_t)b0 * NTOK;
    int b = (int)(row >> 10);
    int n = (int)(row & 1023);
    int h = n >> 5, w = n & 31;
    const float* p  = g_logit + row * NTOK;
    const float* ph = g_P + ((size_t)b * 64 + h) * 1024;
    const float* pw = g_P + ((size_t)b * 64 + 32 + w) * 1024;
    int tid = threadIdx.x;

    float4 v = *(const float4*)&p[tid * 4];
    float4 bh = *(const float4*)&ph[tid * 4];
    float4 bw = *(const float4*)&pw[tid * 4];
    v.x += bh.x + bw.x; v.y += bh.y + bw.y;
    v.z += bh.z + bw.z; v.w += bh.w + bw.w;

    float m = fmaxf(fmaxf(v.x, v.y), fmaxf(v.z, v.w));
#pragma unroll
    for (int o = 16; o; o >>= 1) m = fmaxf(m, __shfl_xor_sync(~0u, m, o));
    __shared__ float red[8];
    if ((tid & 31) == 0) red[tid >> 5] = m;
    __syncthreads();
    float bm = red[0];
#pragma unroll
    for (int i = 1; i < 8; i++) bm = fmaxf(bm, red[i]);
    __syncthreads();

    v.x = __expf(v.x - bm); v.y = __expf(v.y - bm);
    v.z = __expf(v.z - bm); v.w = __expf(v.w - bm);
    float s = v.x + v.y + v.z + v.w;
#pragma unroll
    for (int o = 16; o; o >>= 1) s += __shfl_xor_sync(~0u, s, o);
    if ((tid & 31) == 0) red[tid >> 5] = s;
    __syncthreads();
    float bs = 0.f;
#pragma unroll
    for (int i = 0; i < 8; i++) bs += red[i];
    float inv = 1.0f / bs;

    __half2 a0; a0.x = __float2half_rn(v.x * inv); a0.y = __float2half_rn(v.y * inv);
    __half2 a1; a1.x = __float2half_rn(v.z * inv); a1.y = __float2half_rn(v.w * inv);
    size_t off = row * NTOK + tid * 4;
    *reinterpret_cast<__half2*>(g_att16 + off) = a0;
    *reinterpret_cast<__half2*>(g_att16 + off + 2) = a1;
}

// ---------------------------------------------------------------------------
extern "C" void kernel_launch(void* const* d_in, const int* in_sizes, int n_in,
                              void* d_out, int out_size) {
    const float* x     = (const float*)d_in[0];
    const float* Wmat  = (const float*)d_in[1];
    const float* rel_h = (const float*)d_in[2];
    const float* rel_w = (const float*)d_in[3];
    float* out = (float*)d_out;

    static cudaStream_t s1 = nullptr, s2 = nullptr;
    static cudaEvent_t eF1, eF2, eX0, eX1, eM, eL0, eL1, eS0, eS1, eV0, eV1;
    if (s1 == nullptr) {
        cudaStreamCreateWithFlags(&s1, cudaStreamNonBlocking);
        cudaStreamCreateWithFlags(&s2, cudaStreamNonBlocking);
        cudaEvent_t* evs[11] = {&eF1, &eF2, &eX0, &eX1, &eM, &eL0, &eL1, &eS0, &eS1, &eV0, &eV1};
        for (int i = 0; i < 11; i++) cudaEventCreateWithFlags(evs[i], cudaEventDisableTiming);
        cudaFuncSetAttribute(gemm3<0>,   cudaFuncAttributeMaxDynamicSharedMemorySize, SMEM_MAIN);
        cudaFuncSetAttribute(gemm3<1>,   cudaFuncAttributeMaxDynamicSharedMemorySize, SMEM_MAIN);
        cudaFuncSetAttribute(p_gemm,     cudaFuncAttributeMaxDynamicSharedMemorySize, SMEM_P);
        cudaFuncSetAttribute(h1_gemm<0>, cudaFuncAttributeMaxDynamicSharedMemorySize, SMEM_U);
        cudaFuncSetAttribute(h1_gemm<1>, cudaFuncAttributeMaxDynamicSharedMemorySize, SMEM_U);
    }

    // fork side streams (every wait below follows its record in issue order)
    cudaEventRecord(eF1, 0);
    cudaStreamWaitEvent(s1, eF1, 0);
    cudaEventRecord(eF2, 0);
    cudaStreamWaitEvent(s2, eF2, 0);

    // main: x transpose halves
    transpose_x<<<dim3(32, 8, HB), dim3(32, 8)>>>(x, 0);
    cudaEventRecord(eX0, 0);
    transpose_x<<<dim3(32, 8, HB), dim3(32, 8)>>>(x, HB);
    cudaEventRecord(eX1, 0);

    // s1: W preps -> M, G; P halves
    transpose_w<<<dim3(48, 16), dim3(32, 8), 0, s1>>>(Wmat);
    sgemm_split<0><<<dim3(8, 8), 256, 0, s1>>>();                  // M
    cudaEventRecord(eM, s1);
    prep_rhw<<<(64 * 512 + 255) / 256, 256, 0, s1>>>(rel_h, rel_w);
    sgemm_split<1><<<dim3(8, 1), 256, 0, s1>>>();                  // G
    cudaStreamWaitEvent(s1, eX0, 0);
    p_gemm<<<dim3(8, 1, HB), 256, SMEM_P, s1>>>(0);
    cudaStreamWaitEvent(s1, eX1, 0);
    p_gemm<<<dim3(8, 1, HB), 256, SMEM_P, s1>>>(HB);

    // s2: Wv prep -> v halves
    prep_w16<<<(512 * 512 + 255) / 256, 256, 0, s2>>>(Wmat);
    cudaStreamWaitEvent(s2, eX0, 0);
    h1_gemm<0><<<dim3(8, 4, HB), 128, SMEM_U, s2>>>(nullptr, 0);
    cudaEventRecord(eV0, s2);
    cudaStreamWaitEvent(s2, eX1, 0);
    h1_gemm<0><<<dim3(8, 4, HB), 128, SMEM_U, s2>>>(nullptr, HB);
    cudaEventRecord(eV1, s2);

    // main: T -> logits halves (records BEFORE any wait on eL*)
    cudaStreamWaitEvent(0, eM, 0);
    gemm3<0><<<dim3(4, 8, HB), 128, SMEM_MAIN>>>(0);
    gemm3<0><<<dim3(4, 8, HB), 128, SMEM_MAIN>>>(HB);
    gemm3<1><<<dim3(8, 8, HB), 128, SMEM_MAIN>>>(0);
    cudaEventRecord(eL0, 0);
    gemm3<1><<<dim3(8, 8, HB), 128, SMEM_MAIN>>>(HB);
    cudaEventRecord(eL1, 0);

    // s1: softmax halves (waits issued AFTER the records above)
    cudaStreamWaitEvent(s1, eL0, 0);
    softmax_bias<<<HB * NTOK, 256, 0, s1>>>(0);
    cudaEventRecord(eS0, s1);
    cudaStreamWaitEvent(s1, eL1, 0);
    softmax_bias<<<HB * NTOK, 256, 0, s1>>>(HB);
    cudaEventRecord(eS1, s1);

    // main: out halves
    cudaStreamWaitEvent(0, eS0, 0);
    cudaStreamWaitEvent(0, eV0, 0);
    h1_gemm<1><<<dim3(8, 4, HB), 128, SMEM_U>>>(out, 0);
    cudaStreamWaitEvent(0, eS1, 0);
    cudaStreamWaitEvent(0, eV1, 0);
    h1_gemm<1><<<dim3(8, 4, HB), 128, SMEM_U>>>(out, HB);
}

// round 13
// speedup vs baseline: 1.1363x; 1.1363x over previous
#include <cuda_runtime.h>
#include <cuda_bf16.h>
#include <cuda_fp16.h>
#include <cstdint>

#define BATCH 64
#define CDIM  512
#define NTOK  1024

typedef __nv_bfloat16 bf;

// ---------------- scratch (device globals) ----------------------------------
__device__ float g_WT [(size_t)512 * 1536];
__device__ float g_rhw[(size_t)64 * 512];
__device__ bf g_Mh[(size_t)512 * 512];
__device__ bf g_Mm[(size_t)512 * 512];
__device__ bf g_Gh[(size_t)64 * 512];
__device__ bf g_Gm[(size_t)64 * 512];
__device__ bf g_xTh[(size_t)BATCH * NTOK * CDIM];
__device__ bf g_xTm[(size_t)BATCH * NTOK * CDIM];
__device__ __half g_xT16[(size_t)BATCH * NTOK * CDIM];
__device__ __half g_W16h[(size_t)512 * 512];
__device__ __half g_T16h[(size_t)BATCH * NTOK * 512];   // T^T fp16 hi
__device__ __half g_T16l[(size_t)BATCH * NTOK * 512];   // T^T fp16 lo
__device__ float  g_logit[(size_t)BATCH * NTOK * NTOK];
__device__ float  g_P[(size_t)BATCH * 64 * NTOK];
__device__ __half g_v16[(size_t)BATCH * CDIM * NTOK];
__device__ __half g_att16[(size_t)BATCH * NTOK * NTOK];

// ---------------- PTX helpers ----------------------------------------------
__device__ __forceinline__ uint32_t smem_u32(const void* p) {
    uint32_t a;
    asm("{ .reg .u64 t; cvta.to.shared.u64 t, %1; cvt.u32.u64 %0, t; }" : "=r"(a) : "l"(p));
    return a;
}
__device__ __forceinline__ void cpa16(uint32_t dst, const void* src) {
    asm volatile("cp.async.cg.shared.global [%0], [%1], 16;" :: "r"(dst), "l"(src));
}
__device__ __forceinline__ void ldsm4(uint32_t r[4], uint32_t addr) {
    asm volatile("ldmatrix.sync.aligned.m8n8.x4.shared.b16 {%0,%1,%2,%3}, [%4];"
                 : "=r"(r[0]), "=r"(r[1]), "=r"(r[2]), "=r"(r[3]) : "r"(addr));
}
__device__ __forceinline__ void mma16816(float c[4], const uint32_t a[4], const uint32_t b[2]) {
    asm volatile("mma.sync.aligned.m16n8k16.row.col.f32.bf16.bf16.f32 "
                 "{%0,%1,%2,%3}, {%4,%5,%6,%7}, {%8,%9}, {%0,%1,%2,%3};"
                 : "+f"(c[0]), "+f"(c[1]), "+f"(c[2]), "+f"(c[3])
                 : "r"(a[0]), "r"(a[1]), "r"(a[2]), "r"(a[3]), "r"(b[0]), "r"(b[1]));
}
__device__ __forceinline__ void mma16816h(float c[4], const uint32_t a[4], const uint32_t b[2]) {
    asm volatile("mma.sync.aligned.m16n8k16.row.col.f32.f16.f16.f32 "
                 "{%0,%1,%2,%3}, {%4,%5,%6,%7}, {%8,%9}, {%0,%1,%2,%3};"
                 : "+f"(c[0]), "+f"(c[1]), "+f"(c[2]), "+f"(c[3])
                 : "r"(a[0]), "r"(a[1]), "r"(a[2]), "r"(a[3]), "r"(b[0]), "r"(b[1]));
}
__device__ __forceinline__ uint32_t sw_off(int row, int chunk) {
    return (uint32_t)(row * 64 + ((chunk ^ ((row >> 1) & 3)) << 4));
}
__device__ __forceinline__ void split_store(bf* __restrict__ ph, bf* __restrict__ pm,
                                            size_t off, float v0, float v1) {
    bf h0 = __float2bfloat16(v0), h1 = __float2bfloat16(v1);
    bf m0 = __float2bfloat16(v0 - __bfloat162float(h0));
    bf m1 = __float2bfloat16(v1 - __bfloat162float(h1));
    __nv_bfloat162 hh; hh.x = h0; hh.y = h1;
    __nv_bfloat162 mm; mm.x = m0; mm.y = m1;
    *reinterpret_cast<__nv_bfloat162*>(ph + off) = hh;
    *reinterpret_cast<__nv_bfloat162*>(pm + off) = mm;
}
__device__ __forceinline__ void split_store_f16(__half* __restrict__ ph, __half* __restrict__ pl,
                                                size_t off, float v0, float v1) {
    __half h0 = __float2half_rn(v0), h1 = __float2half_rn(v1);
    __half l0 = __float2half_rn(v0 - __half2float(h0));
    __half l1 = __float2half_rn(v1 - __half2float(h1));
    __half2 hh; hh.x = h0; hh.y = h1;
    __half2 ll; ll.x = l0; ll.y = l1;
    *reinterpret_cast<__half2*>(ph + off) = hh;
    *reinterpret_cast<__half2*>(pl + off) = ll;
}

// ======= T GEMM: 3-term bf16, 128x128 tile, 4 warps; fp16 hi/lo output ======
// T^T[b][m][c1] = sum_c2 xT[m][c2] * M[c1][c2]     K=512
#define OFF_AH 0
#define OFF_AM 8192
#define OFF_BH 16384
#define OFF_BM 24576
#define STAGE_BYTES 32768
#define NSTAGE 3
#define SMEM_MAIN (NSTAGE * STAGE_BYTES)

__global__ __launch_bounds__(128, 2) void t_gemm() {
    extern __shared__ __align__(128) char smem[];
    const uint32_t sbase = smem_u32(smem);
    const int tid = threadIdx.x;
    const int wid = tid >> 5, lane = tid & 31;
    const int b = blockIdx.z;
    const int nBase = blockIdx.x * 128;
    const int mBase = blockIdx.y * 128;
    const int wm = (wid >> 1) * 64, wn = (wid & 1) * 64;

    constexpr int NIT = 16;
    const size_t bXT = (size_t)b << 19;

    float acc[4][8][4];
#pragma unroll
    for (int i = 0; i < 4; i++)
#pragma unroll
        for (int j = 0; j < 8; j++)
#pragma unroll
            for (int k = 0; k < 4; k++) acc[i][j][k] = 0.f;

    auto issue_stage = [&](int stage, int kt) {
        const bf* pah = g_xTh + bXT + (size_t)mBase * 512 + kt;
        const bf* pam = g_xTm + bXT + (size_t)mBase * 512 + kt;
        const bf* pbh = g_Mh + (size_t)nBase * 512 + kt;
        const bf* pbm = g_Mm + (size_t)nBase * 512 + kt;
        const uint32_t sb = sbase + stage * STAGE_BYTES;
#pragma unroll
        for (int j = 0; j < 4; j++) {
            const int idx = tid + j * 128;
            const int row = idx >> 2, ch = idx & 3;
            const uint32_t d = sw_off(row, ch);
            const int s = row * 512 + ch * 8;
            cpa16(sb + OFF_AH + d, pah + s);
            cpa16(sb + OFF_AM + d, pam + s);
            cpa16(sb + OFF_BH + d, pbh + s);
            cpa16(sb + OFF_BM + d, pbm + s);
        }
        asm volatile("cp.async.commit_group;");
    };

    auto compute = [&](int stage) {
        const uint32_t base = sbase + stage * STAGE_BYTES;
        const int sel = lane >> 3;
#pragma unroll
        for (int k8 = 0; k8 < 2; k8++) {
            uint32_t bhf[8][2], bmf[8][2];
#pragma unroll
            for (int pr = 0; pr < 4; pr++) {
                const int nt = 2 * pr + (sel >> 1);
                const int kb = sel & 1;
                const uint32_t ra = base + OFF_BH + sw_off(wn + nt * 8 + (lane & 7), k8 * 2 + kb);
                uint32_t r[4];
                ldsm4(r, ra);
                bhf[2 * pr][0] = r[0]; bhf[2 * pr][1] = r[1];
                bhf[2 * pr + 1][0] = r[2]; bhf[2 * pr + 1][1] = r[3];
                ldsm4(r, ra + (OFF_BM - OFF_BH));
                bmf[2 * pr][0] = r[0]; bmf[2 * pr][1] = r[1];
                bmf[2 * pr + 1][0] = r[2]; bmf[2 * pr + 1][1] = r[3];
            }
#pragma unroll
            for (int mt = 0; mt < 4; mt++) {
                const uint32_t aa = base + OFF_AH +
                    sw_off(wm + mt * 16 + (sel & 1) * 8 + (lane & 7), k8 * 2 + (sel >> 1));
                uint32_t ah[4], am[4];
                ldsm4(ah, aa);
                ldsm4(am, aa + (OFF_AM - OFF_AH));
#pragma unroll
                for (int nt = 0; nt < 8; nt++) mma16816(acc[mt][nt], ah, bhf[nt]);
#pragma unroll
                for (int nt = 0; nt < 8; nt++) mma16816(acc[mt][nt], ah, bmf[nt]);
#pragma unroll
                for (int nt = 0; nt < 8; nt++) mma16816(acc[mt][nt], am, bhf[nt]);
            }
        }
    };

    issue_stage(0, 0);
    issue_stage(1, 32);
    for (int it = 0; it < NIT; it++) {
        if (it + 2 < NIT) asm volatile("cp.async.wait_group 1;");
        else              asm volatile("cp.async.wait_group 0;");
        __syncthreads();
        if (it + 2 < NIT) issue_stage((it + 2) % NSTAGE, (it + 2) * 32);
        compute(it % NSTAGE);
    }

    const int lr = lane >> 2, lc = 2 * (lane & 3);
#pragma unroll
    for (int mt = 0; mt < 4; mt++) {
#pragma unroll
        for (int nt = 0; nt < 8; nt++) {
            const int r0 = mBase + wm + mt * 16 + lr;
            const int c0 = nBase + wn + nt * 8 + lc;
            split_store_f16(g_T16h + bXT, g_T16l + bXT, (size_t)r0 * 512 + c0, acc[mt][nt][0], acc[mt][nt][1]);
            split_store_f16(g_T16h + bXT, g_T16l + bXT, (size_t)(r0 + 8) * 512 + c0, acc[mt][nt][2], acc[mt][nt][3]);
        }
    }
}

// ======= logits GEMM: 2-term fp16 (A=x16 single, B=T16 hi/lo), K=512 ========
#define L_A  0
#define L_BH 8192
#define L_BL 16384
#define L_STAGE 24576
#define SMEM_L (NSTAGE * L_STAGE)

__global__ __launch_bounds__(128, 2) void logit_gemm() {
    extern __shared__ __align__(128) char smem[];
    const uint32_t sbase = smem_u32(smem);
    const int tid = threadIdx.x;
    const int wid = tid >> 5, lane = tid & 31;
    const int b = blockIdx.z;
    const int nBase = blockIdx.x * 128;   // logit cols m (B = T rows)
    const int mBase = blockIdx.y * 128;   // logit rows n (A = x rows)
    const int wm = (wid >> 1) * 64, wn = (wid & 1) * 64;
    const size_t bXT = (size_t)b << 19;
    const size_t bQK = (size_t)b << 20;

    float acc[4][8][4];
#pragma unroll
    for (int i = 0; i < 4; i++)
#pragma unroll
        for (int j = 0; j < 8; j++)
#pragma unroll
            for (int k = 0; k < 4; k++) acc[i][j][k] = 0.f;

    auto issue_stage = [&](int stage, int kt) {
        const __half* pa  = g_xT16 + bXT + (size_t)mBase * 512 + kt;
        const __half* pbh = g_T16h + bXT + (size_t)nBase * 512 + kt;
        const __half* pbl = g_T16l + bXT + (size_t)nBase * 512 + kt;
        const uint32_t sb = sbase + stage * L_STAGE;
#pragma unroll
        for (int j = 0; j < 4; j++) {
            const int idx = tid + j * 128;
            const int row = idx >> 2, ch = idx & 3;
            const uint32_t d = sw_off(row, ch);
            const int s = row * 512 + ch * 8;
            cpa16(sb + L_A  + d, pa  + s);
            cpa16(sb + L_BH + d, pbh + s);
            cpa16(sb + L_BL + d, pbl + s);
        }
        asm volatile("cp.async.commit_group;");
    };

    auto compute = [&](int stage) {
        const uint32_t base = sbase + stage * L_STAGE;
        const int sel = lane >> 3;
#pragma unroll
        for (int k8 = 0; k8 < 2; k8++) {
            uint32_t bhf[8][2], blf[8][2];
#pragma unroll
            for (int pr = 0; pr < 4; pr++) {
                const int nt = 2 * pr + (sel >> 1);
                const int kb = sel & 1;
                const uint32_t ra = base + L_BH + sw_off(wn + nt * 8 + (lane & 7), k8 * 2 + kb);
                uint32_t r[4];
                ldsm4(r, ra);
                bhf[2 * pr][0] = r[0]; bhf[2 * pr][1] = r[1];
                bhf[2 * pr + 1][0] = r[2]; bhf[2 * pr + 1][1] = r[3];
                ldsm4(r, ra + (L_BL - L_BH));
                blf[2 * pr][0] = r[0]; blf[2 * pr][1] = r[1];
                blf[2 * pr + 1][0] = r[2]; blf[2 * pr + 1][1] = r[3];
            }
#pragma unroll
            for (int mt = 0; mt < 4; mt++) {
                const uint32_t aa = base + L_A +
                    sw_off(wm + mt * 16 + (sel & 1) * 8 + (lane & 7), k8 * 2 + (sel >> 1));
                uint32_t ah[4];
                ldsm4(ah, aa);
#pragma unroll
                for (int nt = 0; nt < 8; nt++) mma16816h(acc[mt][nt], ah, bhf[nt]);
#pragma unroll
                for (int nt = 0; nt < 8; nt++) mma16816h(acc[mt][nt], ah, blf[nt]);
            }
        }
    };

    issue_stage(0, 0);
    issue_stage(1, 32);
    for (int it = 0; it < 16; it++) {
        if (it + 2 < 16) asm volatile("cp.async.wait_group 1;");
        else             asm volatile("cp.async.wait_group 0;");
        __syncthreads();
        if (it + 2 < 16) issue_stage((it + 2) % NSTAGE, (it + 2) * 32);
        compute(it % NSTAGE);
    }

    const int lr = lane >> 2, lc = 2 * (lane & 3);
#pragma unroll
    for (int mt = 0; mt < 4; mt++) {
#pragma unroll
        for (int nt = 0; nt < 8; nt++) {
            const int r0 = mBase + wm + mt * 16 + lr;
            const int c0 = nBase + wn + nt * 8 + lc;
            float2 v0; v0.x = acc[mt][nt][0]; v0.y = acc[mt][nt][1];
            float2 v1; v1.x = acc[mt][nt][2]; v1.y = acc[mt][nt][3];
            *reinterpret_cast<float2*>(g_logit + bQK + (size_t)r0 * 1024 + c0) = v0;
            *reinterpret_cast<float2*>(g_logit + bQK + (size_t)(r0 + 8) * 1024 + c0) = v1;
        }
    }
}

// ================= P GEMM: P[b][r][m] = G[r][:] . xT[m][:] ==================
#define P_AH 0
#define P_AM 4096
#define P_BH 8192
#define P_BM 16384
#define P_STAGE 24576
#define SMEM_P (NSTAGE * P_STAGE)

__global__ __launch_bounds__(256, 2) void p_gemm() {
    extern __shared__ __align__(128) char smem[];
    const uint32_t sbase = smem_u32(smem);
    const int tid = threadIdx.x;
    const int wid = tid >> 5, lane = tid & 31;
    const int b = blockIdx.z;
    const int nBase = blockIdx.x * 128;
    const int wm = (wid >> 2) * 32, wn = (wid & 3) * 32;
    const size_t bXT = (size_t)b << 19;

    float acc[2][4][4];
#pragma unroll
    for (int i = 0; i < 2; i++)
#pragma unroll
        for (int j = 0; j < 4; j++)
#pragma unroll
            for (int k = 0; k < 4; k++) acc[i][j][k] = 0.f;

    auto issue_stage = [&](int stage, int kt) {
        const uint32_t sb = sbase + stage * P_STAGE;
        {
            const int row = tid >> 2, ch = tid & 3;
            const uint32_t d = sw_off(row, ch);
            const int s = row * 512 + kt + ch * 8;
            cpa16(sb + P_AH + d, g_Gh + s);
            cpa16(sb + P_AM + d, g_Gm + s);
        }
#pragma unroll
        for (int j = 0; j < 2; j++) {
            const int idx = tid + j * 256;
            const int row = idx >> 2, ch = idx & 3;
            const uint32_t d = sw_off(row, ch);
            const size_t s = bXT + (size_t)(nBase + row) * 512 + kt + ch * 8;
            cpa16(sb + P_BH + d, g_xTh + s);
            cpa16(sb + P_BM + d, g_xTm + s);
        }
        asm volatile("cp.async.commit_group;");
    };

    auto compute = [&](int stage) {
        const uint32_t base = sbase + stage * P_STAGE;
        const int sel = lane >> 3;
#pragma unroll
        for (int k8 = 0; k8 < 2; k8++) {
            uint32_t bhf[4][2], bmf[4][2];
#pragma unroll
            for (int pr = 0; pr < 2; pr++) {
                const int nt = 2 * pr + (sel >> 1);
                const int kb = sel & 1;
                const uint32_t ra = base + P_BH + sw_off(wn + nt * 8 + (lane & 7), k8 * 2 + kb);
                uint32_t r[4];
                ldsm4(r, ra);
                bhf[2 * pr][0] = r[0]; bhf[2 * pr][1] = r[1];
                bhf[2 * pr + 1][0] = r[2]; bhf[2 * pr + 1][1] = r[3];
                ldsm4(r, ra + (P_BM - P_BH));
                bmf[2 * pr][0] = r[0]; bmf[2 * pr][1] = r[1];
                bmf[2 * pr + 1][0] = r[2]; bmf[2 * pr + 1][1] = r[3];
            }
#pragma unroll
            for (int mt = 0; mt < 2; mt++) {
                const uint32_t aa = base + P_AH +
                    sw_off(wm + mt * 16 + (sel & 1) * 8 + (lane & 7), k8 * 2 + (sel >> 1));
                uint32_t ah[4], am[4];
                ldsm4(ah, aa);
                ldsm4(am, aa + (P_AM - P_AH));
#pragma unroll
                for (int nt = 0; nt < 4; nt++) mma16816(acc[mt][nt], ah, bhf[nt]);
#pragma unroll
                for (int nt = 0; nt < 4; nt++) mma16816(acc[mt][nt], ah, bmf[nt]);
#pragma unroll
                for (int nt = 0; nt < 4; nt++) mma16816(acc[mt][nt], am, bhf[nt]);
            }
        }
    };

    issue_stage(0, 0);
    issue_stage(1, 32);
    for (int it = 0; it < 16; it++) {
        if (it + 2 < 16) asm volatile("cp.async.wait_group 1;");
        else             asm volatile("cp.async.wait_group 0;");
        __syncthreads();
        if (it + 2 < 16) issue_stage((it + 2) % NSTAGE, (it + 2) * 32);
        compute(it % NSTAGE);
    }

    const int lr = lane >> 2, lc = 2 * (lane & 3);
    float* P = g_P + (size_t)b * 64 * 1024;
#pragma unroll
    for (int mt = 0; mt < 2; mt++) {
#pragma unroll
        for (int nt = 0; nt < 4; nt++) {
            const int r0 = wm + mt * 16 + lr;
            const int c0 = nBase + wn + nt * 8 + lc;
            float2 v0; v0.x = acc[mt][nt][0]; v0.y = acc[mt][nt][1];
            float2 v1; v1.x = acc[mt][nt][2]; v1.y = acc[mt][nt][3];
            *reinterpret_cast<float2*>(P + (size_t)r0 * 1024 + c0) = v0;
            *reinterpret_cast<float2*>(P + (size_t)(r0 + 8) * 1024 + c0) = v1;
        }
    }
}

// ======= fp16 single-term GEMM: 128x128 tile, 4 warps =======================
#define U_A  0
#define U_B  8192
#define U_STAGE 16384
#define SMEM_U (NSTAGE * U_STAGE)

template <int MODE>
__global__ __launch_bounds__(128, 2) void h1_gemm(float* __restrict__ outp) {
    extern __shared__ __align__(128) char smem[];
    const uint32_t sbase = smem_u32(smem);
    const int tid = threadIdx.x;
    const int wid = tid >> 5, lane = tid & 31;
    const int b = blockIdx.z;
    const int nBase = blockIdx.x * 128;
    const int mBase = blockIdx.y * 128;
    const int wm = (wid >> 1) * 64, wn = (wid & 1) * 64;
    const size_t bQK = (size_t)b << 20;
    const size_t bXT = (size_t)b << 19;

    constexpr int NIT = (MODE == 0) ? 16 : 32;
    constexpr int LD  = (MODE == 0) ? 512 : 1024;

    float acc[4][8][4];
#pragma unroll
    for (int i = 0; i < 4; i++)
#pragma unroll
        for (int j = 0; j < 8; j++)
#pragma unroll
            for (int k = 0; k < 4; k++) acc[i][j][k] = 0.f;

    auto issue_stage = [&](int stage, int kt) {
        const __half *pa, *pb;
        if (MODE == 0) {
            pa = g_W16h + (size_t)mBase * 512 + kt;
            pb = g_xT16 + bXT + (size_t)nBase * 512 + kt;
        } else {
            pa = g_v16 + bXT + (size_t)mBase * 1024 + kt;
            pb = g_att16 + bQK + (size_t)nBase * 1024 + kt;
        }
        const uint32_t sb = sbase + stage * U_STAGE;
#pragma unroll
        for (int j = 0; j < 4; j++) {
            const int idx = tid + j * 128;
            const int row = idx >> 2, ch = idx & 3;
            const uint32_t d = sw_off(row, ch);
            const int s = row * LD + ch * 8;
            cpa16(sb + U_A + d, pa + s);
            cpa16(sb + U_B + d, pb + s);
        }
        asm volatile("cp.async.commit_group;");
    };

    auto compute = [&](int stage) {
        const uint32_t base = sbase + stage * U_STAGE;
        const int sel = lane >> 3;
#pragma unroll
        for (int k8 = 0; k8 < 2; k8++) {
            uint32_t bff[8][2];
#pragma unroll
            for (int pr = 0; pr < 4; pr++) {
                const int nt = 2 * pr + (sel >> 1);
                const int kb = sel & 1;
                uint32_t r[4];
                ldsm4(r, base + U_B + sw_off(wn + nt * 8 + (lane & 7), k8 * 2 + kb));
                bff[2 * pr][0] = r[0]; bff[2 * pr][1] = r[1];
                bff[2 * pr + 1][0] = r[2]; bff[2 * pr + 1][1] = r[3];
            }
#pragma unroll
            for (int mt = 0; mt < 4; mt++) {
                const uint32_t aa = base + U_A +
                    sw_off(wm + mt * 16 + (sel & 1) * 8 + (lane & 7), k8 * 2 + (sel >> 1));
                uint32_t ah[4];
                ldsm4(ah, aa);
#pragma unroll
                for (int nt = 0; nt < 8; nt++) mma16816h(acc[mt][nt], ah, bff[nt]);
            }
        }
    };

    issue_stage(0, 0);
    issue_stage(1, 32);
    for (int it = 0; it < NIT; it++) {
        if (it + 2 < NIT) asm volatile("cp.async.wait_group 1;");
        else              asm volatile("cp.async.wait_group 0;");
        __syncthreads();
        if (it + 2 < NIT) issue_stage((it + 2) % NSTAGE, (it + 2) * 32);
        compute(it % NSTAGE);
    }

    const int lr = lane >> 2, lc = 2 * (lane & 3);
#pragma unroll
    for (int mt = 0; mt < 4; mt++) {
#pragma unroll
        for (int nt = 0; nt < 8; nt++) {
            const int r0 = mBase + wm + mt * 16 + lr;
            const int c0 = nBase + wn + nt * 8 + lc;
            if (MODE == 0) {
                __half* ov = g_v16 + bXT;
                __half2 h0; h0.x = __float2half_rn(acc[mt][nt][0]); h0.y = __float2half_rn(acc[mt][nt][1]);
                __half2 h1; h1.x = __float2half_rn(acc[mt][nt][2]); h1.y = __float2half_rn(acc[mt][nt][3]);
                *reinterpret_cast<__half2*>(ov + (size_t)r0 * 1024 + c0) = h0;
                *reinterpret_cast<__half2*>(ov + (size_t)(r0 + 8) * 1024 + c0) = h1;
            } else {
                float* of = outp + bXT;
                float2 v0; v0.x = acc[mt][nt][0]; v0.y = acc[mt][nt][1];
                float2 v1; v1.x = acc[mt][nt][2]; v1.y = acc[mt][nt][3];
                *reinterpret_cast<float2*>(of + (size_t)r0 * 1024 + c0) = v0;
                *reinterpret_cast<float2*>(of + (size_t)(r0 + 8) * 1024 + c0) = v1;
            }
        }
    }
}

// ---------------- small fp32 GEMM for M and G precompute --------------------
template <int IS_G>
__global__ __launch_bounds__(256) void sgemm_split() {
    const float* A = IS_G ? g_rhw : g_WT;
    const int lda = IS_G ? 512 : 1536;
    const float* B = IS_G ? g_WT : (g_WT + 512);
    const int ldb = 1536;
    bf* Ch = IS_G ? g_Gh : g_Mh;
    bf* Cm = IS_G ? g_Gm : g_Mm;

    __shared__ float As[16][72];
    __shared__ float Bs[16][72];
    const int tid = threadIdx.x;
    const int tx = tid & 15, ty = tid >> 4;
    const int rBase = blockIdx.y * 64, cBase = blockIdx.x * 64;

    float acc[4][4];
#pragma unroll
    for (int i = 0; i < 4; i++)
#pragma unroll
        for (int j = 0; j < 4; j++) acc[i][j] = 0.f;

    for (int kt = 0; kt < 512; kt += 16) {
        const int row = tid >> 2, q = (tid & 3) * 4;
        float4 va = *(const float4*)&A[(size_t)(rBase + row) * lda + kt + q];
        As[q + 0][row] = va.x; As[q + 1][row] = va.y;
        As[q + 2][row] = va.z; As[q + 3][row] = va.w;
        float4 vb = *(const float4*)&B[(size_t)(cBase + row) * ldb + kt + q];
        Bs[q + 0][row] = vb.x; Bs[q + 1][row] = vb.y;
        Bs[q + 2][row] = vb.z; Bs[q + 3][row] = vb.w;
        __syncthreads();
#pragma unroll
        for (int k = 0; k < 16; k++) {
            float a[4], bb[4];
            *(float4*)&a[0]  = *(const float4*)&As[k][ty * 4];
            *(float4*)&bb[0] = *(const float4*)&Bs[k][tx * 4];
#pragma unroll
            for (int i = 0; i < 4; i++)
#pragma unroll
                for (int j = 0; j < 4; j++) acc[i][j] += a[i] * bb[j];
        }
        __syncthreads();
    }
#pragma unroll
    for (int i = 0; i < 4; i++) {
        const int row = rBase + ty * 4 + i;
        const int col = cBase + tx * 4;
        split_store(Ch, Cm, (size_t)row * 512 + col, acc[i][0], acc[i][1]);
        split_store(Ch, Cm, (size_t)row * 512 + col + 2, acc[i][2], acc[i][3]);
    }
}

// ---------------- prep kernels ----------------------------------------------
__global__ void transpose_w(const float* __restrict__ W) {
    __shared__ float t[32][33];
    int o0 = blockIdx.x * 32, c0 = blockIdx.y * 32;
    int tx = threadIdx.x, ty = threadIdx.y;
#pragma unroll
    for (int j = 0; j < 32; j += 8)
        t[ty + j][tx] = W[(size_t)(o0 + ty + j) * 512 + c0 + tx];
    __syncthreads();
#pragma unroll
    for (int j = 0; j < 32; j += 8)
        g_WT[(size_t)(c0 + ty + j) * 1536 + o0 + tx] = t[tx][ty + j];
}

__global__ void prep_rhw(const float* __restrict__ rel_h, const float* __restrict__ rel_w) {
    int idx = blockIdx.x * blockDim.x + threadIdx.x;
    if (idx >= 64 * 512) return;
    int r = idx >> 9, c = idx & 511;
    g_rhw[idx] = (r < 32) ? rel_h[c * 32 + r] : rel_w[c * 32 + (r - 32)];
}

__global__ void prep_w16(const float* __restrict__ W) {
    int idx = blockIdx.x * blockDim.x + threadIdx.x;
    if (idx >= 512 * 512) return;
    int cv = idx >> 9, c = idx & 511;
    g_W16h[idx] = __float2half_rn(W[(size_t)(1024 + cv) * 512 + c]);
}

__global__ void transpose_x(const float* __restrict__ x) {
    __shared__ float t[64][33];
    int b = blockIdx.z;
    int n0 = blockIdx.x * 32, c0 = blockIdx.y * 64;
    const float* src = x + (size_t)b * CDIM * NTOK;
    size_t dbase = (size_t)b * NTOK * CDIM;
    int tx = threadIdx.x, ty = threadIdx.y;
#pragma unroll
    for (int j = 0; j < 8; j++)
        t[ty + j * 8][tx] = src[(size_t)(c0 + ty + j * 8) * NTOK + n0 + tx];
    __syncthreads();
#pragma unroll
    for (int j = 0; j < 4; j++) {
        int n = ty + j * 8;
        float v0 = t[2 * tx][n], v1 = t[2 * tx + 1][n];
        size_t off = dbase + (size_t)(n0 + n) * CDIM + c0 + 2 * tx;
        bf h0 = __float2bfloat16(v0), h1 = __float2bfloat16(v1);
        __nv_bfloat162 hh; hh.x = h0; hh.y = h1;
        __nv_bfloat162 mm;
        mm.x = __float2bfloat16(v0 - __bfloat162float(h0));
        mm.y = __float2bfloat16(v1 - __bfloat162float(h1));
        __half2 xx; xx.x = __float2half_rn(v0); xx.y = __float2half_rn(v1);
        *reinterpret_cast<__nv_bfloat162*>(g_xTh + off) = hh;
        *reinterpret_cast<__nv_bfloat162*>(g_xTm + off) = mm;
        *reinterpret_cast<__half2*>(g_xT16 + off) = xx;
    }
}

// softmax over m with fused pos-bias; writes fp16 att
__global__ __launch_bounds__(256) void softmax_bias() {
    size_t row = blockIdx.x;
    int b = (int)(row >> 10);
    int n = (int)(row & 1023);
    int h = n >> 5, w = n & 31;
    const float* p  = g_logit + row * NTOK;
    const float* ph = g_P + ((size_t)b * 64 + h) * 1024;
    const float* pw = g_P + ((size_t)b * 64 + 32 + w) * 1024;
    int tid = threadIdx.x;

    float4 v = *(const float4*)&p[tid * 4];
    float4 bh = *(const float4*)&ph[tid * 4];
    float4 bw = *(const float4*)&pw[tid * 4];
    v.x += bh.x + bw.x; v.y += bh.y + bw.y;
    v.z += bh.z + bw.z; v.w += bh.w + bw.w;

    float m = fmaxf(fmaxf(v.x, v.y), fmaxf(v.z, v.w));
#pragma unroll
    for (int o = 16; o; o >>= 1) m = fmaxf(m, __shfl_xor_sync(~0u, m, o));
    __shared__ float red[8];
    if ((tid & 31) == 0) red[tid >> 5] = m;
    __syncthreads();
    float bm = red[0];
#pragma unroll
    for (int i = 1; i < 8; i++) bm = fmaxf(bm, red[i]);
    __syncthreads();

    v.x = __expf(v.x - bm); v.y = __expf(v.y - bm);
    v.z = __expf(v.z - bm); v.w = __expf(v.w - bm);
    float s = v.x + v.y + v.z + v.w;
#pragma unroll
    for (int o = 16; o; o >>= 1) s += __shfl_xor_sync(~0u, s, o);
    if ((tid & 31) == 0) red[tid >> 5] = s;
    __syncthreads();
    float bs = 0.f;
#pragma unroll
    for (int i = 0; i < 8; i++) bs += red[i];
    float inv = 1.0f / bs;

    __half2 a0; a0.x = __float2half_rn(v.x * inv); a0.y = __float2half_rn(v.y * inv);
    __half2 a1; a1.x = __float2half_rn(v.z * inv); a1.y = __float2half_rn(v.w * inv);
    size_t off = row * NTOK + tid * 4;
    *reinterpret_cast<__half2*>(g_att16 + off) = a0;
    *reinterpret_cast<__half2*>(g_att16 + off + 2) = a1;
}

// ---------------------------------------------------------------------------
extern "C" void kernel_launch(void* const* d_in, const int* in_sizes, int n_in,
                              void* d_out, int out_size) {
    const float* x     = (const float*)d_in[0];
    const float* Wmat  = (const float*)d_in[1];
    const float* rel_h = (const float*)d_in[2];
    const float* rel_w = (const float*)d_in[3];
    float* out = (float*)d_out;

    static cudaStream_t s1 = nullptr, s2 = nullptr;
    static cudaEvent_t eF1, eF2, eX, eM, eP, eV;
    if (s1 == nullptr) {
        cudaStreamCreateWithFlags(&s1, cudaStreamNonBlocking);
        cudaStreamCreateWithFlags(&s2, cudaStreamNonBlocking);
        cudaEventCreateWithFlags(&eF1, cudaEventDisableTiming);
        cudaEventCreateWithFlags(&eF2, cudaEventDisableTiming);
        cudaEventCreateWithFlags(&eX,  cudaEventDisableTiming);
        cudaEventCreateWithFlags(&eM,  cudaEventDisableTiming);
        cudaEventCreateWithFlags(&eP,  cudaEventDisableTiming);
        cudaEventCreateWithFlags(&eV,  cudaEventDisableTiming);
        cudaFuncSetAttribute(t_gemm,     cudaFuncAttributeMaxDynamicSharedMemorySize, SMEM_MAIN);
        cudaFuncSetAttribute(logit_gemm, cudaFuncAttributeMaxDynamicSharedMemorySize, SMEM_L);
        cudaFuncSetAttribute(p_gemm,     cudaFuncAttributeMaxDynamicSharedMemorySize, SMEM_P);
        cudaFuncSetAttribute(h1_gemm<0>, cudaFuncAttributeMaxDynamicSharedMemorySize, SMEM_U);
        cudaFuncSetAttribute(h1_gemm<1>, cudaFuncAttributeMaxDynamicSharedMemorySize, SMEM_U);
    }

    // fork side streams
    cudaEventRecord(eF1, 0);
    cudaStreamWaitEvent(s1, eF1, 0);
    cudaEventRecord(eF2, 0);
    cudaStreamWaitEvent(s2, eF2, 0);

    // main: x transpose/split
    transpose_x<<<dim3(32, 8, 64), dim3(32, 8)>>>(x);
    cudaEventRecord(eX, 0);

    // s1: W preps -> M, G, then P (needs xT)
    transpose_w<<<dim3(48, 16), dim3(32, 8), 0, s1>>>(Wmat);
    sgemm_split<0><<<dim3(8, 8), 256, 0, s1>>>();                 // M
    cudaEventRecord(eM, s1);
    prep_rhw<<<(64 * 512 + 255) / 256, 256, 0, s1>>>(rel_h, rel_w);
    sgemm_split<1><<<dim3(8, 1), 256, 0, s1>>>();                 // G
    cudaStreamWaitEvent(s1, eX, 0);
    p_gemm<<<dim3(8, 1, 64), 256, SMEM_P, s1>>>();                // P
    cudaEventRecord(eP, s1);

    // s2: Wv prep -> v (needs xT16)
    prep_w16<<<(512 * 512 + 255) / 256, 256, 0, s2>>>(Wmat);
    cudaStreamWaitEvent(s2, eX, 0);
    h1_gemm<0><<<dim3(8, 4, 64), 128, SMEM_U, s2>>>(nullptr);     // v fp16
    cudaEventRecord(eV, s2);

    // main: T -> logits
    cudaStreamWaitEvent(0, eM, 0);
    t_gemm<<<dim3(4, 8, 64), 128, SMEM_MAIN>>>();                 // T fp16 hi/lo
    logit_gemm<<<dim3(8, 8, 64), 128, SMEM_L>>>();                // logits (2-term fp16)

    // join P, softmax, join v, out
    cudaStreamWaitEvent(0, eP, 0);
    softmax_bias<<<BATCH * NTOK, 256>>>();
    cudaStreamWaitEvent(0, eV, 0);
    h1_gemm<1><<<dim3(8, 4, 64), 128, SMEM_U>>>(out);
}

// round 14
// speedup vs baseline: 1.2201x; 1.0738x over previous
#include <cuda_runtime.h>
#include <cuda_bf16.h>
#include <cuda_fp16.h>
#include <cstdint>

#define BATCH 64
#define CDIM  512
#define NTOK  1024

// ---------------- scratch (device globals) ----------------------------------
__device__ float g_WT [(size_t)512 * 1536];
__device__ float g_rhw[(size_t)64 * 512];
__device__ __half g_M16h[(size_t)512 * 512];
__device__ __half g_M16l[(size_t)512 * 512];
__device__ __half g_G16h[(size_t)64 * 512];
__device__ __half g_G16l[(size_t)64 * 512];
__device__ __half g_xT16 [(size_t)BATCH * NTOK * CDIM];   // [b][n][c] fp16 hi
__device__ __half g_xT16l[(size_t)BATCH * NTOK * CDIM];   // fp16 lo
__device__ __half g_W16h[(size_t)512 * 512];
__device__ __half g_T16h[(size_t)BATCH * NTOK * 512];     // T^T fp16 hi
__device__ __half g_T16l[(size_t)BATCH * NTOK * 512];     // T^T fp16 lo
__device__ float  g_logit[(size_t)BATCH * NTOK * NTOK];
__device__ float  g_P[(size_t)BATCH * 64 * NTOK];
__device__ __half g_v16[(size_t)BATCH * CDIM * NTOK];
__device__ __half g_att16[(size_t)BATCH * NTOK * NTOK];

// ---------------- PTX helpers ----------------------------------------------
__device__ __forceinline__ uint32_t smem_u32(const void* p) {
    uint32_t a;
    asm("{ .reg .u64 t; cvta.to.shared.u64 t, %1; cvt.u32.u64 %0, t; }" : "=r"(a) : "l"(p));
    return a;
}
__device__ __forceinline__ void cpa16(uint32_t dst, const void* src) {
    asm volatile("cp.async.cg.shared.global [%0], [%1], 16;" :: "r"(dst), "l"(src));
}
__device__ __forceinline__ void ldsm4(uint32_t r[4], uint32_t addr) {
    asm volatile("ldmatrix.sync.aligned.m8n8.x4.shared.b16 {%0,%1,%2,%3}, [%4];"
                 : "=r"(r[0]), "=r"(r[1]), "=r"(r[2]), "=r"(r[3]) : "r"(addr));
}
__device__ __forceinline__ void mma16816h(float c[4], const uint32_t a[4], const uint32_t b[2]) {
    asm volatile("mma.sync.aligned.m16n8k16.row.col.f32.f16.f16.f32 "
                 "{%0,%1,%2,%3}, {%4,%5,%6,%7}, {%8,%9}, {%0,%1,%2,%3};"
                 : "+f"(c[0]), "+f"(c[1]), "+f"(c[2]), "+f"(c[3])
                 : "r"(a[0]), "r"(a[1]), "r"(a[2]), "r"(a[3]), "r"(b[0]), "r"(b[1]));
}
__device__ __forceinline__ uint32_t sw_off(int row, int chunk) {
    return (uint32_t)(row * 64 + ((chunk ^ ((row >> 1) & 3)) << 4));
}
__device__ __forceinline__ void split_store_f16(__half* __restrict__ ph, __half* __restrict__ pl,
                                                size_t off, float v0, float v1) {
    __half h0 = __float2half_rn(v0), h1 = __float2half_rn(v1);
    __half l0 = __float2half_rn(v0 - __half2float(h0));
    __half l1 = __float2half_rn(v1 - __half2float(h1));
    __half2 hh; hh.x = h0; hh.y = h1;
    __half2 ll; ll.x = l0; ll.y = l1;
    *reinterpret_cast<__half2*>(ph + off) = hh;
    *reinterpret_cast<__half2*>(pl + off) = ll;
}

#define NSTAGE 3

// ======= 2-term fp16 GEMM (A single, B hi/lo): T and logits =================
// MODE 0: T^T[b][m][c1] = sum_c2 x16[m][c2] * M16(h+l)[c1][c2]   K=512
// MODE 1: logit[b][n][m] = sum_c1 x16[n][c1] * T16(h+l)[m][c1]   K=512
#define L_A  0
#define L_BH 8192
#define L_BL 16384
#define L_STAGE 24576
#define SMEM_L (NSTAGE * L_STAGE)

template <int MODE>
__global__ __launch_bounds__(128, 2) void ab2_gemm() {
    extern __shared__ __align__(128) char smem[];
    const uint32_t sbase = smem_u32(smem);
    const int tid = threadIdx.x;
    const int wid = tid >> 5, lane = tid & 31;
    const int b = blockIdx.z;
    const int nBase = blockIdx.x * 128;   // B rows (c1-tile for T, m-tile for logits)
    const int mBase = blockIdx.y * 128;   // A rows
    const int wm = (wid >> 1) * 64, wn = (wid & 1) * 64;
    const size_t bXT = (size_t)b << 19;
    const size_t bQK = (size_t)b << 20;

    float acc[4][8][4];
#pragma unroll
    for (int i = 0; i < 4; i++)
#pragma unroll
        for (int j = 0; j < 8; j++)
#pragma unroll
            for (int k = 0; k < 4; k++) acc[i][j][k] = 0.f;

    auto issue_stage = [&](int stage, int kt) {
        const __half* pa = g_xT16 + bXT + (size_t)mBase * 512 + kt;
        const __half *pbh, *pbl;
        if (MODE == 0) {
            pbh = g_M16h + (size_t)nBase * 512 + kt;
            pbl = g_M16l + (size_t)nBase * 512 + kt;
        } else {
            pbh = g_T16h + bXT + (size_t)nBase * 512 + kt;
            pbl = g_T16l + bXT + (size_t)nBase * 512 + kt;
        }
        const uint32_t sb = sbase + stage * L_STAGE;
#pragma unroll
        for (int j = 0; j < 4; j++) {
            const int idx = tid + j * 128;
            const int row = idx >> 2, ch = idx & 3;
            const uint32_t d = sw_off(row, ch);
            const int s = row * 512 + ch * 8;
            cpa16(sb + L_A  + d, pa  + s);
            cpa16(sb + L_BH + d, pbh + s);
            cpa16(sb + L_BL + d, pbl + s);
        }
        asm volatile("cp.async.commit_group;");
    };

    auto compute = [&](int stage) {
        const uint32_t base = sbase + stage * L_STAGE;
        const int sel = lane >> 3;
#pragma unroll
        for (int k8 = 0; k8 < 2; k8++) {
            uint32_t bhf[8][2], blf[8][2];
#pragma unroll
            for (int pr = 0; pr < 4; pr++) {
                const int nt = 2 * pr + (sel >> 1);
                const int kb = sel & 1;
                const uint32_t ra = base + L_BH + sw_off(wn + nt * 8 + (lane & 7), k8 * 2 + kb);
                uint32_t r[4];
                ldsm4(r, ra);
                bhf[2 * pr][0] = r[0]; bhf[2 * pr][1] = r[1];
                bhf[2 * pr + 1][0] = r[2]; bhf[2 * pr + 1][1] = r[3];
                ldsm4(r, ra + (L_BL - L_BH));
                blf[2 * pr][0] = r[0]; blf[2 * pr][1] = r[1];
                blf[2 * pr + 1][0] = r[2]; blf[2 * pr + 1][1] = r[3];
            }
#pragma unroll
            for (int mt = 0; mt < 4; mt++) {
                const uint32_t aa = base + L_A +
                    sw_off(wm + mt * 16 + (sel & 1) * 8 + (lane & 7), k8 * 2 + (sel >> 1));
                uint32_t ah[4];
                ldsm4(ah, aa);
#pragma unroll
                for (int nt = 0; nt < 8; nt++) mma16816h(acc[mt][nt], ah, bhf[nt]);
#pragma unroll
                for (int nt = 0; nt < 8; nt++) mma16816h(acc[mt][nt], ah, blf[nt]);
            }
        }
    };

    issue_stage(0, 0);
    issue_stage(1, 32);
    for (int it = 0; it < 16; it++) {
        if (it + 2 < 16) asm volatile("cp.async.wait_group 1;");
        else             asm volatile("cp.async.wait_group 0;");
        __syncthreads();
        if (it + 2 < 16) issue_stage((it + 2) % NSTAGE, (it + 2) * 32);
        compute(it % NSTAGE);
    }

    const int lr = lane >> 2, lc = 2 * (lane & 3);
#pragma unroll
    for (int mt = 0; mt < 4; mt++) {
#pragma unroll
        for (int nt = 0; nt < 8; nt++) {
            const int r0 = mBase + wm + mt * 16 + lr;
            const int c0 = nBase + wn + nt * 8 + lc;
            if (MODE == 0) {
                split_store_f16(g_T16h + bXT, g_T16l + bXT, (size_t)r0 * 512 + c0, acc[mt][nt][0], acc[mt][nt][1]);
                split_store_f16(g_T16h + bXT, g_T16l + bXT, (size_t)(r0 + 8) * 512 + c0, acc[mt][nt][2], acc[mt][nt][3]);
            } else {
                float2 v0; v0.x = acc[mt][nt][0]; v0.y = acc[mt][nt][1];
                float2 v1; v1.x = acc[mt][nt][2]; v1.y = acc[mt][nt][3];
                *reinterpret_cast<float2*>(g_logit + bQK + (size_t)r0 * 1024 + c0) = v0;
                *reinterpret_cast<float2*>(g_logit + bQK + (size_t)(r0 + 8) * 1024 + c0) = v1;
            }
        }
    }
}

// ================= P GEMM: 3-term fp16, P[b][r][m] = G[r][:] . x16[m][:] ====
#define P_AH 0
#define P_AM 4096
#define P_BH 8192
#define P_BM 16384
#define P_STAGE 24576
#define SMEM_P (NSTAGE * P_STAGE)

__global__ __launch_bounds__(256, 2) void p_gemm() {
    extern __shared__ __align__(128) char smem[];
    const uint32_t sbase = smem_u32(smem);
    const int tid = threadIdx.x;
    const int wid = tid >> 5, lane = tid & 31;
    const int b = blockIdx.z;
    const int nBase = blockIdx.x * 128;
    const int wm = (wid >> 2) * 32, wn = (wid & 3) * 32;
    const size_t bXT = (size_t)b << 19;

    float acc[2][4][4];
#pragma unroll
    for (int i = 0; i < 2; i++)
#pragma unroll
        for (int j = 0; j < 4; j++)
#pragma unroll
            for (int k = 0; k < 4; k++) acc[i][j][k] = 0.f;

    auto issue_stage = [&](int stage, int kt) {
        const uint32_t sb = sbase + stage * P_STAGE;
        {
            const int row = tid >> 2, ch = tid & 3;
            const uint32_t d = sw_off(row, ch);
            const int s = row * 512 + kt + ch * 8;
            cpa16(sb + P_AH + d, g_G16h + s);
            cpa16(sb + P_AM + d, g_G16l + s);
        }
#pragma unroll
        for (int j = 0; j < 2; j++) {
            const int idx = tid + j * 256;
            const int row = idx >> 2, ch = idx & 3;
            const uint32_t d = sw_off(row, ch);
            const size_t s = bXT + (size_t)(nBase + row) * 512 + kt + ch * 8;
            cpa16(sb + P_BH + d, g_xT16 + s);
            cpa16(sb + P_BM + d, g_xT16l + s);
        }
        asm volatile("cp.async.commit_group;");
    };

    auto compute = [&](int stage) {
        const uint32_t base = sbase + stage * P_STAGE;
        const int sel = lane >> 3;
#pragma unroll
        for (int k8 = 0; k8 < 2; k8++) {
            uint32_t bhf[4][2], bmf[4][2];
#pragma unroll
            for (int pr = 0; pr < 2; pr++) {
                const int nt = 2 * pr + (sel >> 1);
                const int kb = sel & 1;
                const uint32_t ra = base + P_BH + sw_off(wn + nt * 8 + (lane & 7), k8 * 2 + kb);
                uint32_t r[4];
                ldsm4(r, ra);
                bhf[2 * pr][0] = r[0]; bhf[2 * pr][1] = r[1];
                bhf[2 * pr + 1][0] = r[2]; bhf[2 * pr + 1][1] = r[3];
                ldsm4(r, ra + (P_BM - P_BH));
                bmf[2 * pr][0] = r[0]; bmf[2 * pr][1] = r[1];
                bmf[2 * pr + 1][0] = r[2]; bmf[2 * pr + 1][1] = r[3];
            }
#pragma unroll
            for (int mt = 0; mt < 2; mt++) {
                const uint32_t aa = base + P_AH +
                    sw_off(wm + mt * 16 + (sel & 1) * 8 + (lane & 7), k8 * 2 + (sel >> 1));
                uint32_t ah[4], am[4];
                ldsm4(ah, aa);
                ldsm4(am, aa + (P_AM - P_AH));
#pragma unroll
                for (int nt = 0; nt < 4; nt++) mma16816h(acc[mt][nt], ah, bhf[nt]);
#pragma unroll
                for (int nt = 0; nt < 4; nt++) mma16816h(acc[mt][nt], ah, bmf[nt]);
#pragma unroll
                for (int nt = 0; nt < 4; nt++) mma16816h(acc[mt][nt], am, bhf[nt]);
            }
        }
    };

    issue_stage(0, 0);
    issue_stage(1, 32);
    for (int it = 0; it < 16; it++) {
        if (it + 2 < 16) asm volatile("cp.async.wait_group 1;");
        else             asm volatile("cp.async.wait_group 0;");
        __syncthreads();
        if (it + 2 < 16) issue_stage((it + 2) % NSTAGE, (it + 2) * 32);
        compute(it % NSTAGE);
    }

    const int lr = lane >> 2, lc = 2 * (lane & 3);
    float* P = g_P + (size_t)b * 64 * 1024;
#pragma unroll
    for (int mt = 0; mt < 2; mt++) {
#pragma unroll
        for (int nt = 0; nt < 4; nt++) {
            const int r0 = wm + mt * 16 + lr;
            const int c0 = nBase + wn + nt * 8 + lc;
            float2 v0; v0.x = acc[mt][nt][0]; v0.y = acc[mt][nt][1];
            float2 v1; v1.x = acc[mt][nt][2]; v1.y = acc[mt][nt][3];
            *reinterpret_cast<float2*>(P + (size_t)r0 * 1024 + c0) = v0;
            *reinterpret_cast<float2*>(P + (size_t)(r0 + 8) * 1024 + c0) = v1;
        }
    }
}

// ======= fp16 single-term GEMM: 128x128 tile, 4 warps =======================
#define U_A  0
#define U_B  8192
#define U_STAGE 16384
#define SMEM_U (NSTAGE * U_STAGE)

template <int MODE>
__global__ __launch_bounds__(128, 2) void h1_gemm(float* __restrict__ outp) {
    extern __shared__ __align__(128) char smem[];
    const uint32_t sbase = smem_u32(smem);
    const int tid = threadIdx.x;
    const int wid = tid >> 5, lane = tid & 31;
    const int b = blockIdx.z;
    const int nBase = blockIdx.x * 128;
    const int mBase = blockIdx.y * 128;
    const int wm = (wid >> 1) * 64, wn = (wid & 1) * 64;
    const size_t bQK = (size_t)b << 20;
    const size_t bXT = (size_t)b << 19;

    constexpr int NIT = (MODE == 0) ? 16 : 32;
    constexpr int LD  = (MODE == 0) ? 512 : 1024;

    float acc[4][8][4];
#pragma unroll
    for (int i = 0; i < 4; i++)
#pragma unroll
        for (int j = 0; j < 8; j++)
#pragma unroll
            for (int k = 0; k < 4; k++) acc[i][j][k] = 0.f;

    auto issue_stage = [&](int stage, int kt) {
        const __half *pa, *pb;
        if (MODE == 0) {
            pa = g_W16h + (size_t)mBase * 512 + kt;
            pb = g_xT16 + bXT + (size_t)nBase * 512 + kt;
        } else {
            pa = g_v16 + bXT + (size_t)mBase * 1024 + kt;
            pb = g_att16 + bQK + (size_t)nBase * 1024 + kt;
        }
        const uint32_t sb = sbase + stage * U_STAGE;
#pragma unroll
        for (int j = 0; j < 4; j++) {
            const int idx = tid + j * 128;
            const int row = idx >> 2, ch = idx & 3;
            const uint32_t d = sw_off(row, ch);
            const int s = row * LD + ch * 8;
            cpa16(sb + U_A + d, pa + s);
            cpa16(sb + U_B + d, pb + s);
        }
        asm volatile("cp.async.commit_group;");
    };

    auto compute = [&](int stage) {
        const uint32_t base = sbase + stage * U_STAGE;
        const int sel = lane >> 3;
#pragma unroll
        for (int k8 = 0; k8 < 2; k8++) {
            uint32_t bff[8][2];
#pragma unroll
            for (int pr = 0; pr < 4; pr++) {
                const int nt = 2 * pr + (sel >> 1);
                const int kb = sel & 1;
                uint32_t r[4];
                ldsm4(r, base + U_B + sw_off(wn + nt * 8 + (lane & 7), k8 * 2 + kb));
                bff[2 * pr][0] = r[0]; bff[2 * pr][1] = r[1];
                bff[2 * pr + 1][0] = r[2]; bff[2 * pr + 1][1] = r[3];
            }
#pragma unroll
            for (int mt = 0; mt < 4; mt++) {
                const uint32_t aa = base + U_A +
                    sw_off(wm + mt * 16 + (sel & 1) * 8 + (lane & 7), k8 * 2 + (sel >> 1));
                uint32_t ah[4];
                ldsm4(ah, aa);
#pragma unroll
                for (int nt = 0; nt < 8; nt++) mma16816h(acc[mt][nt], ah, bff[nt]);
            }
        }
    };

    issue_stage(0, 0);
    issue_stage(1, 32);
    for (int it = 0; it < NIT; it++) {
        if (it + 2 < NIT) asm volatile("cp.async.wait_group 1;");
        else              asm volatile("cp.async.wait_group 0;");
        __syncthreads();
        if (it + 2 < NIT) issue_stage((it + 2) % NSTAGE, (it + 2) * 32);
        compute(it % NSTAGE);
    }

    const int lr = lane >> 2, lc = 2 * (lane & 3);
#pragma unroll
    for (int mt = 0; mt < 4; mt++) {
#pragma unroll
        for (int nt = 0; nt < 8; nt++) {
            const int r0 = mBase + wm + mt * 16 + lr;
            const int c0 = nBase + wn + nt * 8 + lc;
            if (MODE == 0) {
                __half* ov = g_v16 + bXT;
                __half2 h0; h0.x = __float2half_rn(acc[mt][nt][0]); h0.y = __float2half_rn(acc[mt][nt][1]);
                __half2 h1; h1.x = __float2half_rn(acc[mt][nt][2]); h1.y = __float2half_rn(acc[mt][nt][3]);
                *reinterpret_cast<__half2*>(ov + (size_t)r0 * 1024 + c0) = h0;
                *reinterpret_cast<__half2*>(ov + (size_t)(r0 + 8) * 1024 + c0) = h1;
            } else {
                float* of = outp + bXT;
                float2 v0; v0.x = acc[mt][nt][0]; v0.y = acc[mt][nt][1];
                float2 v1; v1.x = acc[mt][nt][2]; v1.y = acc[mt][nt][3];
                *reinterpret_cast<float2*>(of + (size_t)r0 * 1024 + c0) = v0;
                *reinterpret_cast<float2*>(of + (size_t)(r0 + 8) * 1024 + c0) = v1;
            }
        }
    }
}

// ---------------- small fp32 GEMM for M and G precompute (fp16 out) ---------
template <int IS_G>
__global__ __launch_bounds__(256) void sgemm_split() {
    const float* A = IS_G ? g_rhw : g_WT;
    const int lda = IS_G ? 512 : 1536;
    const float* B = IS_G ? g_WT : (g_WT + 512);
    const int ldb = 1536;
    __half* Ch = IS_G ? g_G16h : g_M16h;
    __half* Cl = IS_G ? g_G16l : g_M16l;

    __shared__ float As[16][72];
    __shared__ float Bs[16][72];
    const int tid = threadIdx.x;
    const int tx = tid & 15, ty = tid >> 4;
    const int rBase = blockIdx.y * 64, cBase = blockIdx.x * 64;

    float acc[4][4];
#pragma unroll
    for (int i = 0; i < 4; i++)
#pragma unroll
        for (int j = 0; j < 4; j++) acc[i][j] = 0.f;

    for (int kt = 0; kt < 512; kt += 16) {
        const int row = tid >> 2, q = (tid & 3) * 4;
        float4 va = *(const float4*)&A[(size_t)(rBase + row) * lda + kt + q];
        As[q + 0][row] = va.x; As[q + 1][row] = va.y;
        As[q + 2][row] = va.z; As[q + 3][row] = va.w;
        float4 vb = *(const float4*)&B[(size_t)(cBase + row) * ldb + kt + q];
        Bs[q + 0][row] = vb.x; Bs[q + 1][row] = vb.y;
        Bs[q + 2][row] = vb.z; Bs[q + 3][row] = vb.w;
        __syncthreads();
#pragma unroll
        for (int k = 0; k < 16; k++) {
            float a[4], bb[4];
            *(float4*)&a[0]  = *(const float4*)&As[k][ty * 4];
            *(float4*)&bb[0] = *(const float4*)&Bs[k][tx * 4];
#pragma unroll
            for (int i = 0; i < 4; i++)
#pragma unroll
                for (int j = 0; j < 4; j++) acc[i][j] += a[i] * bb[j];
        }
        __syncthreads();
    }
#pragma unroll
    for (int i = 0; i < 4; i++) {
        const int row = rBase + ty * 4 + i;
        const int col = cBase + tx * 4;
        split_store_f16(Ch, Cl, (size_t)row * 512 + col, acc[i][0], acc[i][1]);
        split_store_f16(Ch, Cl, (size_t)row * 512 + col + 2, acc[i][2], acc[i][3]);
    }
}

// ---------------- prep kernels ----------------------------------------------
__global__ void transpose_w(const float* __restrict__ W) {
    __shared__ float t[32][33];
    int o0 = blockIdx.x * 32, c0 = blockIdx.y * 32;
    int tx = threadIdx.x, ty = threadIdx.y;
#pragma unroll
    for (int j = 0; j < 32; j += 8)
        t[ty + j][tx] = W[(size_t)(o0 + ty + j) * 512 + c0 + tx];
    __syncthreads();
#pragma unroll
    for (int j = 0; j < 32; j += 8)
        g_WT[(size_t)(c0 + ty + j) * 1536 + o0 + tx] = t[tx][ty + j];
}

__global__ void prep_rhw(const float* __restrict__ rel_h, const float* __restrict__ rel_w) {
    int idx = blockIdx.x * blockDim.x + threadIdx.x;
    if (idx >= 64 * 512) return;
    int r = idx >> 9, c = idx & 511;
    g_rhw[idx] = (r < 32) ? rel_h[c * 32 + r] : rel_w[c * 32 + (r - 32)];
}

__global__ void prep_w16(const float* __restrict__ W) {
    int idx = blockIdx.x * blockDim.x + threadIdx.x;
    if (idx >= 512 * 512) return;
    int cv = idx >> 9, c = idx & 511;
    g_W16h[idx] = __float2half_rn(W[(size_t)(1024 + cv) * 512 + c]);
}

// transpose + fp16 hi/lo split
__global__ void transpose_x(const float* __restrict__ x) {
    __shared__ float t[64][33];
    int b = blockIdx.z;
    int n0 = blockIdx.x * 32, c0 = blockIdx.y * 64;
    const float* src = x + (size_t)b * CDIM * NTOK;
    size_t dbase = (size_t)b * NTOK * CDIM;
    int tx = threadIdx.x, ty = threadIdx.y;
#pragma unroll
    for (int j = 0; j < 8; j++)
        t[ty + j * 8][tx] = src[(size_t)(c0 + ty + j * 8) * NTOK + n0 + tx];
    __syncthreads();
#pragma unroll
    for (int j = 0; j < 4; j++) {
        int n = ty + j * 8;
        float v0 = t[2 * tx][n], v1 = t[2 * tx + 1][n];
        size_t off = dbase + (size_t)(n0 + n) * CDIM + c0 + 2 * tx;
        split_store_f16(g_xT16, g_xT16l, off, v0, v1);
    }
}

// softmax over m with fused pos-bias; writes fp16 att
__global__ __launch_bounds__(256) void softmax_bias() {
    size_t row = blockIdx.x;
    int b = (int)(row >> 10);
    int n = (int)(row & 1023);
    int h = n >> 5, w = n & 31;
    const float* p  = g_logit + row * NTOK;
    const float* ph = g_P + ((size_t)b * 64 + h) * 1024;
    const float* pw = g_P + ((size_t)b * 64 + 32 + w) * 1024;
    int tid = threadIdx.x;

    float4 v = *(const float4*)&p[tid * 4];
    float4 bh = *(const float4*)&ph[tid * 4];
    float4 bw = *(const float4*)&pw[tid * 4];
    v.x += bh.x + bw.x; v.y += bh.y + bw.y;
    v.z += bh.z + bw.z; v.w += bh.w + bw.w;

    float m = fmaxf(fmaxf(v.x, v.y), fmaxf(v.z, v.w));
#pragma unroll
    for (int o = 16; o; o >>= 1) m = fmaxf(m, __shfl_xor_sync(~0u, m, o));
    __shared__ float red[8];
    if ((tid & 31) == 0) red[tid >> 5] = m;
    __syncthreads();
    float bm = red[0];
#pragma unroll
    for (int i = 1; i < 8; i++) bm = fmaxf(bm, red[i]);
    __syncthreads();

    v.x = __expf(v.x - bm); v.y = __expf(v.y - bm);
    v.z = __expf(v.z - bm); v.w = __expf(v.w - bm);
    float s = v.x + v.y + v.z + v.w;
#pragma unroll
    for (int o = 16; o; o >>= 1) s += __shfl_xor_sync(~0u, s, o);
    if ((tid & 31) == 0) red[tid >> 5] = s;
    __syncthreads();
    float bs = 0.f;
#pragma unroll
    for (int i = 0; i < 8; i++) bs += red[i];
    float inv = 1.0f / bs;

    __half2 a0; a0.x = __float2half_rn(v.x * inv); a0.y = __float2half_rn(v.y * inv);
    __half2 a1; a1.x = __float2half_rn(v.z * inv); a1.y = __float2half_rn(v.w * inv);
    size_t off = row * NTOK + tid * 4;
    *reinterpret_cast<__half2*>(g_att16 + off) = a0;
    *reinterpret_cast<__half2*>(g_att16 + off + 2) = a1;
}

// ---------------------------------------------------------------------------
extern "C" void kernel_launch(void* const* d_in, const int* in_sizes, int n_in,
                              void* d_out, int out_size) {
    const float* x     = (const float*)d_in[0];
    const float* Wmat  = (const float*)d_in[1];
    const float* rel_h = (const float*)d_in[2];
    const float* rel_w = (const float*)d_in[3];
    float* out = (float*)d_out;

    static cudaStream_t s1 = nullptr, s2 = nullptr;
    static cudaEvent_t eF1, eF2, eX, eM, eP, eV;
    if (s1 == nullptr) {
        cudaStreamCreateWithFlags(&s1, cudaStreamNonBlocking);
        cudaStreamCreateWithFlags(&s2, cudaStreamNonBlocking);
        cudaEventCreateWithFlags(&eF1, cudaEventDisableTiming);
        cudaEventCreateWithFlags(&eF2, cudaEventDisableTiming);
        cudaEventCreateWithFlags(&eX,  cudaEventDisableTiming);
        cudaEventCreateWithFlags(&eM,  cudaEventDisableTiming);
        cudaEventCreateWithFlags(&eP,  cudaEventDisableTiming);
        cudaEventCreateWithFlags(&eV,  cudaEventDisableTiming);
        cudaFuncSetAttribute(ab2_gemm<0>, cudaFuncAttributeMaxDynamicSharedMemorySize, SMEM_L);
        cudaFuncSetAttribute(ab2_gemm<1>, cudaFuncAttributeMaxDynamicSharedMemorySize, SMEM_L);
        cudaFuncSetAttribute(p_gemm,      cudaFuncAttributeMaxDynamicSharedMemorySize, SMEM_P);
        cudaFuncSetAttribute(h1_gemm<0>,  cudaFuncAttributeMaxDynamicSharedMemorySize, SMEM_U);
        cudaFuncSetAttribute(h1_gemm<1>,  cudaFuncAttributeMaxDynamicSharedMemorySize, SMEM_U);
    }

    // fork side streams
    cudaEventRecord(eF1, 0);
    cudaStreamWaitEvent(s1, eF1, 0);
    cudaEventRecord(eF2, 0);
    cudaStreamWaitEvent(s2, eF2, 0);

    // main: x transpose/split
    transpose_x<<<dim3(32, 8, 64), dim3(32, 8)>>>(x);
    cudaEventRecord(eX, 0);

    // s1: W preps -> M, G, then P (needs xT)
    transpose_w<<<dim3(48, 16), dim3(32, 8), 0, s1>>>(Wmat);
    sgemm_split<0><<<dim3(8, 8), 256, 0, s1>>>();                 // M fp16 h/l
    cudaEventRecord(eM, s1);
    prep_rhw<<<(64 * 512 + 255) / 256, 256, 0, s1>>>(rel_h, rel_w);
    sgemm_split<1><<<dim3(8, 1), 256, 0, s1>>>();                 // G fp16 h/l
    cudaStreamWaitEvent(s1, eX, 0);
    p_gemm<<<dim3(8, 1, 64), 256, SMEM_P, s1>>>();                // P
    cudaEventRecord(eP, s1);

    // s2: Wv prep -> v (needs xT16)
    prep_w16<<<(512 * 512 + 255) / 256, 256, 0, s2>>>(Wmat);
    cudaStreamWaitEvent(s2, eX, 0);
    h1_gemm<0><<<dim3(8, 4, 64), 128, SMEM_U, s2>>>(nullptr);     // v fp16
    cudaEventRecord(eV, s2);

    // main: T -> logits (both 2-term fp16)
    cudaStreamWaitEvent(0, eM, 0);
    ab2_gemm<0><<<dim3(4, 8, 64), 128, SMEM_L>>>();               // T fp16 h/l
    ab2_gemm<1><<<dim3(8, 8, 64), 128, SMEM_L>>>();               // logits

    // join P, softmax, join v, out
    cudaStreamWaitEvent(0, eP, 0);
    softmax_bias<<<BATCH * NTOK, 256>>>();
    cudaStreamWaitEvent(0, eV, 0);
    h1_gemm<1><<<dim3(8, 4, 64), 128, SMEM_U>>>(out);
}

// round 15
// speedup vs baseline: 1.4372x; 1.1779x over previous
#include <cuda_runtime.h>
#include <cuda_bf16.h>
#include <cuda_fp16.h>
#include <cstdint>

#define BATCH 64
#define CDIM  512
#define NTOK  1024

// ---------------- scratch (device globals) ----------------------------------
__device__ float g_WT [(size_t)512 * 1536];
__device__ float g_rhw[(size_t)64 * 512];
__device__ __half g_M16h[(size_t)512 * 512];
__device__ __half g_M16l[(size_t)512 * 512];
__device__ __half g_G16h[(size_t)64 * 512];
__device__ __half g_G16l[(size_t)64 * 512];
__device__ __half g_xT16 [(size_t)BATCH * NTOK * CDIM];   // [b][n][c] fp16 hi
__device__ __half g_xT16l[(size_t)BATCH * NTOK * CDIM];   // fp16 lo
__device__ __half g_W16h[(size_t)512 * 512];
__device__ __half g_T16h[(size_t)BATCH * NTOK * 512];     // T^T fp16 (single)
__device__ float  g_logit[(size_t)BATCH * NTOK * NTOK];
__device__ float  g_P[(size_t)BATCH * 64 * NTOK];
__device__ __half g_v16[(size_t)BATCH * CDIM * NTOK];
__device__ __half g_att16[(size_t)BATCH * NTOK * NTOK];

// ---------------- PTX helpers ----------------------------------------------
__device__ __forceinline__ uint32_t smem_u32(const void* p) {
    uint32_t a;
    asm("{ .reg .u64 t; cvta.to.shared.u64 t, %1; cvt.u32.u64 %0, t; }" : "=r"(a) : "l"(p));
    return a;
}
__device__ __forceinline__ void cpa16(uint32_t dst, const void* src) {
    asm volatile("cp.async.cg.shared.global [%0], [%1], 16;" :: "r"(dst), "l"(src));
}
__device__ __forceinline__ void ldsm4(uint32_t r[4], uint32_t addr) {
    asm volatile("ldmatrix.sync.aligned.m8n8.x4.shared.b16 {%0,%1,%2,%3}, [%4];"
                 : "=r"(r[0]), "=r"(r[1]), "=r"(r[2]), "=r"(r[3]) : "r"(addr));
}
__device__ __forceinline__ void mma16816h(float c[4], const uint32_t a[4], const uint32_t b[2]) {
    asm volatile("mma.sync.aligned.m16n8k16.row.col.f32.f16.f16.f32 "
                 "{%0,%1,%2,%3}, {%4,%5,%6,%7}, {%8,%9}, {%0,%1,%2,%3};"
                 : "+f"(c[0]), "+f"(c[1]), "+f"(c[2]), "+f"(c[3])
                 : "r"(a[0]), "r"(a[1]), "r"(a[2]), "r"(a[3]), "r"(b[0]), "r"(b[1]));
}
__device__ __forceinline__ uint32_t sw_off(int row, int chunk) {
    return (uint32_t)(row * 64 + ((chunk ^ ((row >> 1) & 3)) << 4));
}
__device__ __forceinline__ void split_store_f16(__half* __restrict__ ph, __half* __restrict__ pl,
                                                size_t off, float v0, float v1) {
    __half h0 = __float2half_rn(v0), h1 = __float2half_rn(v1);
    __half l0 = __float2half_rn(v0 - __half2float(h0));
    __half l1 = __float2half_rn(v1 - __half2float(h1));
    __half2 hh; hh.x = h0; hh.y = h1;
    __half2 ll; ll.x = l0; ll.y = l1;
    *reinterpret_cast<__half2*>(ph + off) = hh;
    *reinterpret_cast<__half2*>(pl + off) = ll;
}

#define NSTAGE 3

// ======= T GEMM: 2-term fp16 (A=x16 single, B=M16 hi/lo), fp16 out ==========
#define L_A  0
#define L_BH 8192
#define L_BL 16384
#define L_STAGE 24576
#define SMEM_L (NSTAGE * L_STAGE)

__global__ __launch_bounds__(128, 2) void t_gemm() {
    extern __shared__ __align__(128) char smem[];
    const uint32_t sbase = smem_u32(smem);
    const int tid = threadIdx.x;
    const int wid = tid >> 5, lane = tid & 31;
    const int b = blockIdx.z;
    const int nBase = blockIdx.x * 128;   // c1-tile (M rows)
    const int mBase = blockIdx.y * 128;   // m-tile (x rows)
    const int wm = (wid >> 1) * 64, wn = (wid & 1) * 64;
    const size_t bXT = (size_t)b << 19;

    float acc[4][8][4];
#pragma unroll
    for (int i = 0; i < 4; i++)
#pragma unroll
        for (int j = 0; j < 8; j++)
#pragma unroll
            for (int k = 0; k < 4; k++) acc[i][j][k] = 0.f;

    auto issue_stage = [&](int stage, int kt) {
        const __half* pa  = g_xT16 + bXT + (size_t)mBase * 512 + kt;
        const __half* pbh = g_M16h + (size_t)nBase * 512 + kt;
        const __half* pbl = g_M16l + (size_t)nBase * 512 + kt;
        const uint32_t sb = sbase + stage * L_STAGE;
#pragma unroll
        for (int j = 0; j < 4; j++) {
            const int idx = tid + j * 128;
            const int row = idx >> 2, ch = idx & 3;
            const uint32_t d = sw_off(row, ch);
            const int s = row * 512 + ch * 8;
            cpa16(sb + L_A  + d, pa  + s);
            cpa16(sb + L_BH + d, pbh + s);
            cpa16(sb + L_BL + d, pbl + s);
        }
        asm volatile("cp.async.commit_group;");
    };

    auto compute = [&](int stage) {
        const uint32_t base = sbase + stage * L_STAGE;
        const int sel = lane >> 3;
#pragma unroll
        for (int k8 = 0; k8 < 2; k8++) {
            uint32_t bhf[8][2], blf[8][2];
#pragma unroll
            for (int pr = 0; pr < 4; pr++) {
                const int nt = 2 * pr + (sel >> 1);
                const int kb = sel & 1;
                const uint32_t ra = base + L_BH + sw_off(wn + nt * 8 + (lane & 7), k8 * 2 + kb);
                uint32_t r[4];
                ldsm4(r, ra);
                bhf[2 * pr][0] = r[0]; bhf[2 * pr][1] = r[1];
                bhf[2 * pr + 1][0] = r[2]; bhf[2 * pr + 1][1] = r[3];
                ldsm4(r, ra + (L_BL - L_BH));
                blf[2 * pr][0] = r[0]; blf[2 * pr][1] = r[1];
                blf[2 * pr + 1][0] = r[2]; blf[2 * pr + 1][1] = r[3];
            }
#pragma unroll
            for (int mt = 0; mt < 4; mt++) {
                const uint32_t aa = base + L_A +
                    sw_off(wm + mt * 16 + (sel & 1) * 8 + (lane & 7), k8 * 2 + (sel >> 1));
                uint32_t ah[4];
                ldsm4(ah, aa);
#pragma unroll
                for (int nt = 0; nt < 8; nt++) mma16816h(acc[mt][nt], ah, bhf[nt]);
#pragma unroll
                for (int nt = 0; nt < 8; nt++) mma16816h(acc[mt][nt], ah, blf[nt]);
            }
        }
    };

    issue_stage(0, 0);
    issue_stage(1, 32);
    for (int it = 0; it < 16; it++) {
        if (it + 2 < 16) asm volatile("cp.async.wait_group 1;");
        else             asm volatile("cp.async.wait_group 0;");
        __syncthreads();
        if (it + 2 < 16) issue_stage((it + 2) % NSTAGE, (it + 2) * 32);
        compute(it % NSTAGE);
    }

    const int lr = lane >> 2, lc = 2 * (lane & 3);
    __half* oT = g_T16h + bXT;
#pragma unroll
    for (int mt = 0; mt < 4; mt++) {
#pragma unroll
        for (int nt = 0; nt < 8; nt++) {
            const int r0 = mBase + wm + mt * 16 + lr;
            const int c0 = nBase + wn + nt * 8 + lc;
            __half2 h0; h0.x = __float2half_rn(acc[mt][nt][0]); h0.y = __float2half_rn(acc[mt][nt][1]);
            __half2 h1; h1.x = __float2half_rn(acc[mt][nt][2]); h1.y = __float2half_rn(acc[mt][nt][3]);
            *reinterpret_cast<__half2*>(oT + (size_t)r0 * 512 + c0) = h0;
            *reinterpret_cast<__half2*>(oT + (size_t)(r0 + 8) * 512 + c0) = h1;
        }
    }
}

// ================= P GEMM: 3-term fp16, P[b][r][m] = G[r][:] . x16[m][:] ====
#define P_AH 0
#define P_AM 4096
#define P_BH 8192
#define P_BM 16384
#define P_STAGE 24576
#define SMEM_P (NSTAGE * P_STAGE)

__global__ __launch_bounds__(256, 2) void p_gemm() {
    extern __shared__ __align__(128) char smem[];
    const uint32_t sbase = smem_u32(smem);
    const int tid = threadIdx.x;
    const int wid = tid >> 5, lane = tid & 31;
    const int b = blockIdx.z;
    const int nBase = blockIdx.x * 128;
    const int wm = (wid >> 2) * 32, wn = (wid & 3) * 32;
    const size_t bXT = (size_t)b << 19;

    float acc[2][4][4];
#pragma unroll
    for (int i = 0; i < 2; i++)
#pragma unroll
        for (int j = 0; j < 4; j++)
#pragma unroll
            for (int k = 0; k < 4; k++) acc[i][j][k] = 0.f;

    auto issue_stage = [&](int stage, int kt) {
        const uint32_t sb = sbase + stage * P_STAGE;
        {
            const int row = tid >> 2, ch = tid & 3;
            const uint32_t d = sw_off(row, ch);
            const int s = row * 512 + kt + ch * 8;
            cpa16(sb + P_AH + d, g_G16h + s);
            cpa16(sb + P_AM + d, g_G16l + s);
        }
#pragma unroll
        for (int j = 0; j < 2; j++) {
            const int idx = tid + j * 256;
            const int row = idx >> 2, ch = idx & 3;
            const uint32_t d = sw_off(row, ch);
            const size_t s = bXT + (size_t)(nBase + row) * 512 + kt + ch * 8;
            cpa16(sb + P_BH + d, g_xT16 + s);
            cpa16(sb + P_BM + d, g_xT16l + s);
        }
        asm volatile("cp.async.commit_group;");
    };

    auto compute = [&](int stage) {
        const uint32_t base = sbase + stage * P_STAGE;
        const int sel = lane >> 3;
#pragma unroll
        for (int k8 = 0; k8 < 2; k8++) {
            uint32_t bhf[4][2], bmf[4][2];
#pragma unroll
            for (int pr = 0; pr < 2; pr++) {
                const int nt = 2 * pr + (sel >> 1);
                const int kb = sel & 1;
                const uint32_t ra = base + P_BH + sw_off(wn + nt * 8 + (lane & 7), k8 * 2 + kb);
                uint32_t r[4];
                ldsm4(r, ra);
                bhf[2 * pr][0] = r[0]; bhf[2 * pr][1] = r[1];
                bhf[2 * pr + 1][0] = r[2]; bhf[2 * pr + 1][1] = r[3];
                ldsm4(r, ra + (P_BM - P_BH));
                bmf[2 * pr][0] = r[0]; bmf[2 * pr][1] = r[1];
                bmf[2 * pr + 1][0] = r[2]; bmf[2 * pr + 1][1] = r[3];
            }
#pragma unroll
            for (int mt = 0; mt < 2; mt++) {
                const uint32_t aa = base + P_AH +
                    sw_off(wm + mt * 16 + (sel & 1) * 8 + (lane & 7), k8 * 2 + (sel >> 1));
                uint32_t ah[4], am[4];
                ldsm4(ah, aa);
                ldsm4(am, aa + (P_AM - P_AH));
#pragma unroll
                for (int nt = 0; nt < 4; nt++) mma16816h(acc[mt][nt], ah, bhf[nt]);
#pragma unroll
                for (int nt = 0; nt < 4; nt++) mma16816h(acc[mt][nt], ah, bmf[nt]);
#pragma unroll
                for (int nt = 0; nt < 4; nt++) mma16816h(acc[mt][nt], am, bhf[nt]);
            }
        }
    };

    issue_stage(0, 0);
    issue_stage(1, 32);
    for (int it = 0; it < 16; it++) {
        if (it + 2 < 16) asm volatile("cp.async.wait_group 1;");
        else             asm volatile("cp.async.wait_group 0;");
        __syncthreads();
        if (it + 2 < 16) issue_stage((it + 2) % NSTAGE, (it + 2) * 32);
        compute(it % NSTAGE);
    }

    const int lr = lane >> 2, lc = 2 * (lane & 3);
    float* P = g_P + (size_t)b * 64 * 1024;
#pragma unroll
    for (int mt = 0; mt < 2; mt++) {
#pragma unroll
        for (int nt = 0; nt < 4; nt++) {
            const int r0 = wm + mt * 16 + lr;
            const int c0 = nBase + wn + nt * 8 + lc;
            float2 v0; v0.x = acc[mt][nt][0]; v0.y = acc[mt][nt][1];
            float2 v1; v1.x = acc[mt][nt][2]; v1.y = acc[mt][nt][3];
            *reinterpret_cast<float2*>(P + (size_t)r0 * 1024 + c0) = v0;
            *reinterpret_cast<float2*>(P + (size_t)(r0 + 8) * 1024 + c0) = v1;
        }
    }
}

// ======= fp16 single-term GEMM: 128x128 tile, 4 warps =======================
// MODE 0: v[b][c][n]    = W16h[c][:] . x16[n][:]     K=512,  half out
// MODE 1: out[b][c][n]  = v16[c][:] . att16[n][:]    K=1024, fp32 out
// MODE 2: logit[b][n][m]= x16[n][:] . T16[m][:]      K=512,  fp32 out
#define U_A  0
#define U_B  8192
#define U_STAGE 16384
#define SMEM_U (NSTAGE * U_STAGE)

template <int MODE>
__global__ __launch_bounds__(128, 2) void h1_gemm(float* __restrict__ outp) {
    extern __shared__ __align__(128) char smem[];
    const uint32_t sbase = smem_u32(smem);
    const int tid = threadIdx.x;
    const int wid = tid >> 5, lane = tid & 31;
    const int b = blockIdx.z;
    const int nBase = blockIdx.x * 128;
    const int mBase = blockIdx.y * 128;
    const int wm = (wid >> 1) * 64, wn = (wid & 1) * 64;
    const size_t bQK = (size_t)b << 20;
    const size_t bXT = (size_t)b << 19;

    constexpr int NIT = (MODE == 1) ? 32 : 16;
    constexpr int LD  = (MODE == 1) ? 1024 : 512;

    float acc[4][8][4];
#pragma unroll
    for (int i = 0; i < 4; i++)
#pragma unroll
        for (int j = 0; j < 8; j++)
#pragma unroll
            for (int k = 0; k < 4; k++) acc[i][j][k] = 0.f;

    auto issue_stage = [&](int stage, int kt) {
        const __half *pa, *pb;
        if (MODE == 0) {
            pa = g_W16h + (size_t)mBase * 512 + kt;
            pb = g_xT16 + bXT + (size_t)nBase * 512 + kt;
        } else if (MODE == 1) {
            pa = g_v16 + bXT + (size_t)mBase * 1024 + kt;
            pb = g_att16 + bQK + (size_t)nBase * 1024 + kt;
        } else {
            pa = g_xT16 + bXT + (size_t)mBase * 512 + kt;
            pb = g_T16h + bXT + (size_t)nBase * 512 + kt;
        }
        const uint32_t sb = sbase + stage * U_STAGE;
#pragma unroll
        for (int j = 0; j < 4; j++) {
            const int idx = tid + j * 128;
            const int row = idx >> 2, ch = idx & 3;
            const uint32_t d = sw_off(row, ch);
            const int s = row * LD + ch * 8;
            cpa16(sb + U_A + d, pa + s);
            cpa16(sb + U_B + d, pb + s);
        }
        asm volatile("cp.async.commit_group;");
    };

    auto compute = [&](int stage) {
        const uint32_t base = sbase + stage * U_STAGE;
        const int sel = lane >> 3;
#pragma unroll
        for (int k8 = 0; k8 < 2; k8++) {
            uint32_t bff[8][2];
#pragma unroll
            for (int pr = 0; pr < 4; pr++) {
                const int nt = 2 * pr + (sel >> 1);
                const int kb = sel & 1;
                uint32_t r[4];
                ldsm4(r, base + U_B + sw_off(wn + nt * 8 + (lane & 7), k8 * 2 + kb));
                bff[2 * pr][0] = r[0]; bff[2 * pr][1] = r[1];
                bff[2 * pr + 1][0] = r[2]; bff[2 * pr + 1][1] = r[3];
            }
#pragma unroll
            for (int mt = 0; mt < 4; mt++) {
                const uint32_t aa = base + U_A +
                    sw_off(wm + mt * 16 + (sel & 1) * 8 + (lane & 7), k8 * 2 + (sel >> 1));
                uint32_t ah[4];
                ldsm4(ah, aa);
#pragma unroll
                for (int nt = 0; nt < 8; nt++) mma16816h(acc[mt][nt], ah, bff[nt]);
            }
        }
    };

    issue_stage(0, 0);
    issue_stage(1, 32);
    for (int it = 0; it < NIT; it++) {
        if (it + 2 < NIT) asm volatile("cp.async.wait_group 1;");
        else              asm volatile("cp.async.wait_group 0;");
        __syncthreads();
        if (it + 2 < NIT) issue_stage((it + 2) % NSTAGE, (it + 2) * 32);
        compute(it % NSTAGE);
    }

    const int lr = lane >> 2, lc = 2 * (lane & 3);
#pragma unroll
    for (int mt = 0; mt < 4; mt++) {
#pragma unroll
        for (int nt = 0; nt < 8; nt++) {
            const int r0 = mBase + wm + mt * 16 + lr;
            const int c0 = nBase + wn + nt * 8 + lc;
            if (MODE == 0) {
                __half* ov = g_v16 + bXT;
                __half2 h0; h0.x = __float2half_rn(acc[mt][nt][0]); h0.y = __float2half_rn(acc[mt][nt][1]);
                __half2 h1; h1.x = __float2half_rn(acc[mt][nt][2]); h1.y = __float2half_rn(acc[mt][nt][3]);
                *reinterpret_cast<__half2*>(ov + (size_t)r0 * 1024 + c0) = h0;
                *reinterpret_cast<__half2*>(ov + (size_t)(r0 + 8) * 1024 + c0) = h1;
            } else {
                float* of = (MODE == 1) ? (outp + bXT) : (g_logit + bQK);
                float2 v0; v0.x = acc[mt][nt][0]; v0.y = acc[mt][nt][1];
                float2 v1; v1.x = acc[mt][nt][2]; v1.y = acc[mt][nt][3];
                *reinterpret_cast<float2*>(of + (size_t)r0 * 1024 + c0) = v0;
                *reinterpret_cast<float2*>(of + (size_t)(r0 + 8) * 1024 + c0) = v1;
            }
        }
    }
}

// ---------------- small fp32 GEMM for M and G precompute (fp16 out) ---------
template <int IS_G>
__global__ __launch_bounds__(256) void sgemm_split() {
    const float* A = IS_G ? g_rhw : g_WT;
    const int lda = IS_G ? 512 : 1536;
    const float* B = IS_G ? g_WT : (g_WT + 512);
    const int ldb = 1536;
    __half* Ch = IS_G ? g_G16h : g_M16h;
    __half* Cl = IS_G ? g_G16l : g_M16l;

    __shared__ float As[16][72];
    __shared__ float Bs[16][72];
    const int tid = threadIdx.x;
    const int tx = tid & 15, ty = tid >> 4;
    const int rBase = blockIdx.y * 64, cBase = blockIdx.x * 64;

    float acc[4][4];
#pragma unroll
    for (int i = 0; i < 4; i++)
#pragma unroll
        for (int j = 0; j < 4; j++) acc[i][j] = 0.f;

    for (int kt = 0; kt < 512; kt += 16) {
        const int row = tid >> 2, q = (tid & 3) * 4;
        float4 va = *(const float4*)&A[(size_t)(rBase + row) * lda + kt + q];
        As[q + 0][row] = va.x; As[q + 1][row] = va.y;
        As[q + 2][row] = va.z; As[q + 3][row] = va.w;
        float4 vb = *(const float4*)&B[(size_t)(cBase + row) * ldb + kt + q];
        Bs[q + 0][row] = vb.x; Bs[q + 1][row] = vb.y;
        Bs[q + 2][row] = vb.z; Bs[q + 3][row] = vb.w;
        __syncthreads();
#pragma unroll
        for (int k = 0; k < 16; k++) {
            float a[4], bb[4];
            *(float4*)&a[0]  = *(const float4*)&As[k][ty * 4];
            *(float4*)&bb[0] = *(const float4*)&Bs[k][tx * 4];
#pragma unroll
            for (int i = 0; i < 4; i++)
#pragma unroll
                for (int j = 0; j < 4; j++) acc[i][j] += a[i] * bb[j];
        }
        __syncthreads();
    }
#pragma unroll
    for (int i = 0; i < 4; i++) {
        const int row = rBase + ty * 4 + i;
        const int col = cBase + tx * 4;
        split_store_f16(Ch, Cl, (size_t)row * 512 + col, acc[i][0], acc[i][1]);
        split_store_f16(Ch, Cl, (size_t)row * 512 + col + 2, acc[i][2], acc[i][3]);
    }
}

// ---------------- prep kernels ----------------------------------------------
__global__ void transpose_w(const float* __restrict__ W) {
    __shared__ float t[32][33];
    int o0 = blockIdx.x * 32, c0 = blockIdx.y * 32;
    int tx = threadIdx.x, ty = threadIdx.y;
#pragma unroll
    for (int j = 0; j < 32; j += 8)
        t[ty + j][tx] = W[(size_t)(o0 + ty + j) * 512 + c0 + tx];
    __syncthreads();
#pragma unroll
    for (int j = 0; j < 32; j += 8)
        g_WT[(size_t)(c0 + ty + j) * 1536 + o0 + tx] = t[tx][ty + j];
}

__global__ void prep_rhw(const float* __restrict__ rel_h, const float* __restrict__ rel_w) {
    int idx = blockIdx.x * blockDim.x + threadIdx.x;
    if (idx >= 64 * 512) return;
    int r = idx >> 9, c = idx & 511;
    g_rhw[idx] = (r < 32) ? rel_h[c * 32 + r] : rel_w[c * 32 + (r - 32)];
}

__global__ void prep_w16(const float* __restrict__ W) {
    int idx = blockIdx.x * blockDim.x + threadIdx.x;
    if (idx >= 512 * 512) return;
    int cv = idx >> 9, c = idx & 511;
    g_W16h[idx] = __float2half_rn(W[(size_t)(1024 + cv) * 512 + c]);
}

// transpose + fp16 hi/lo split
__global__ void transpose_x(const float* __restrict__ x) {
    __shared__ float t[64][33];
    int b = blockIdx.z;
    int n0 = blockIdx.x * 32, c0 = blockIdx.y * 64;
    const float* src = x + (size_t)b * CDIM * NTOK;
    size_t dbase = (size_t)b * NTOK * CDIM;
    int tx = threadIdx.x, ty = threadIdx.y;
#pragma unroll
    for (int j = 0; j < 8; j++)
        t[ty + j * 8][tx] = src[(size_t)(c0 + ty + j * 8) * NTOK + n0 + tx];
    __syncthreads();
#pragma unroll
    for (int j = 0; j < 4; j++) {
        int n = ty + j * 8;
        float v0 = t[2 * tx][n], v1 = t[2 * tx + 1][n];
        size_t off = dbase + (size_t)(n0 + n) * CDIM + c0 + 2 * tx;
        split_store_f16(g_xT16, g_xT16l, off, v0, v1);
    }
}

// softmax over m with fused pos-bias; writes fp16 att
__global__ __launch_bounds__(256) void softmax_bias() {
    size_t row = blockIdx.x;
    int b = (int)(row >> 10);
    int n = (int)(row & 1023);
    int h = n >> 5, w = n & 31;
    const float* p  = g_logit + row * NTOK;
    const float* ph = g_P + ((size_t)b * 64 + h) * 1024;
    const float* pw = g_P + ((size_t)b * 64 + 32 + w) * 1024;
    int tid = threadIdx.x;

    float4 v = *(const float4*)&p[tid * 4];
    float4 bh = *(const float4*)&ph[tid * 4];
    float4 bw = *(const float4*)&pw[tid * 4];
    v.x += bh.x + bw.x; v.y += bh.y + bw.y;
    v.z += bh.z + bw.z; v.w += bh.w + bw.w;

    float m = fmaxf(fmaxf(v.x, v.y), fmaxf(v.z, v.w));
#pragma unroll
    for (int o = 16; o; o >>= 1) m = fmaxf(m, __shfl_xor_sync(~0u, m, o));
    __shared__ float red[8];
    if ((tid & 31) == 0) red[tid >> 5] = m;
    __syncthreads();
    float bm = red[0];
#pragma unroll
    for (int i = 1; i < 8; i++) bm = fmaxf(bm, red[i]);
    __syncthreads();

    v.x = __expf(v.x - bm); v.y = __expf(v.y - bm);
    v.z = __expf(v.z - bm); v.w = __expf(v.w - bm);
    float s = v.x + v.y + v.z + v.w;
#pragma unroll
    for (int o = 16; o; o >>= 1) s += __shfl_xor_sync(~0u, s, o);
    if ((tid & 31) == 0) red[tid >> 5] = s;
    __syncthreads();
    float bs = 0.f;
#pragma unroll
    for (int i = 0; i < 8; i++) bs += red[i];
    float inv = 1.0f / bs;

    __half2 a0; a0.x = __float2half_rn(v.x * inv); a0.y = __float2half_rn(v.y * inv);
    __half2 a1; a1.x = __float2half_rn(v.z * inv); a1.y = __float2half_rn(v.w * inv);
    size_t off = row * NTOK + tid * 4;
    *reinterpret_cast<__half2*>(g_att16 + off) = a0;
    *reinterpret_cast<__half2*>(g_att16 + off + 2) = a1;
}

// ---------------------------------------------------------------------------
extern "C" void kernel_launch(void* const* d_in, const int* in_sizes, int n_in,
                              void* d_out, int out_size) {
    const float* x     = (const float*)d_in[0];
    const float* Wmat  = (const float*)d_in[1];
    const float* rel_h = (const float*)d_in[2];
    const float* rel_w = (const float*)d_in[3];
    float* out = (float*)d_out;

    static cudaStream_t s1 = nullptr, s2 = nullptr;
    static cudaEvent_t eF1, eF2, eX, eM, eP, eV;
    if (s1 == nullptr) {
        cudaStreamCreateWithFlags(&s1, cudaStreamNonBlocking);
        cudaStreamCreateWithFlags(&s2, cudaStreamNonBlocking);
        cudaEventCreateWithFlags(&eF1, cudaEventDisableTiming);
        cudaEventCreateWithFlags(&eF2, cudaEventDisableTiming);
        cudaEventCreateWithFlags(&eX,  cudaEventDisableTiming);
        cudaEventCreateWithFlags(&eM,  cudaEventDisableTiming);
        cudaEventCreateWithFlags(&eP,  cudaEventDisableTiming);
        cudaEventCreateWithFlags(&eV,  cudaEventDisableTiming);
        cudaFuncSetAttribute(t_gemm,     cudaFuncAttributeMaxDynamicSharedMemorySize, SMEM_L);
        cudaFuncSetAttribute(p_gemm,     cudaFuncAttributeMaxDynamicSharedMemorySize, SMEM_P);
        cudaFuncSetAttribute(h1_gemm<0>, cudaFuncAttributeMaxDynamicSharedMemorySize, SMEM_U);
        cudaFuncSetAttribute(h1_gemm<1>, cudaFuncAttributeMaxDynamicSharedMemorySize, SMEM_U);
        cudaFuncSetAttribute(h1_gemm<2>, cudaFuncAttributeMaxDynamicSharedMemorySize, SMEM_U);
    }

    // fork side streams
    cudaEventRecord(eF1, 0);
    cudaStreamWaitEvent(s1, eF1, 0);
    cudaEventRecord(eF2, 0);
    cudaStreamWaitEvent(s2, eF2, 0);

    // main: x transpose/split
    transpose_x<<<dim3(32, 8, 64), dim3(32, 8)>>>(x);
    cudaEventRecord(eX, 0);

    // s1: W preps -> M, G, then P (needs xT)
    transpose_w<<<dim3(48, 16), dim3(32, 8), 0, s1>>>(Wmat);
    sgemm_split<0><<<dim3(8, 8), 256, 0, s1>>>();                 // M fp16 h/l
    cudaEventRecord(eM, s1);
    prep_rhw<<<(64 * 512 + 255) / 256, 256, 0, s1>>>(rel_h, rel_w);
    sgemm_split<1><<<dim3(8, 1), 256, 0, s1>>>();                 // G fp16 h/l
    cudaStreamWaitEvent(s1, eX, 0);
    p_gemm<<<dim3(8, 1, 64), 256, SMEM_P, s1>>>();                // P
    cudaEventRecord(eP, s1);

    // s2: Wv prep -> v (needs xT16)
    prep_w16<<<(512 * 512 + 255) / 256, 256, 0, s2>>>(Wmat);
    cudaStreamWaitEvent(s2, eX, 0);
    h1_gemm<0><<<dim3(8, 4, 64), 128, SMEM_U, s2>>>(nullptr);     // v fp16
    cudaEventRecord(eV, s2);

    // main: T (2-term) -> logits (single-term)
    cudaStreamWaitEvent(0, eM, 0);
    t_gemm<<<dim3(4, 8, 64), 128, SMEM_L>>>();                    // T fp16
    h1_gemm<2><<<dim3(8, 8, 64), 128, SMEM_U>>>(nullptr);         // logits

    // join P, softmax, join v, out
    cudaStreamWaitEvent(0, eP, 0);
    softmax_bias<<<BATCH * NTOK, 256>>>();
    cudaStreamWaitEvent(0, eV, 0);
    h1_gemm<1><<<dim3(8, 4, 64), 128, SMEM_U>>>(out);
}

// round 16
// speedup vs baseline: 1.5744x; 1.0955x over previous
#include <cuda_runtime.h>
#include <cuda_bf16.h>
#include <cuda_fp16.h>
#include <cstdint>

#define BATCH 64
#define CDIM  512
#define NTOK  1024

// ---------------- scratch (device globals) ----------------------------------
__device__ float g_WT [(size_t)512 * 1536];
__device__ float g_rhw[(size_t)64 * 512];
__device__ __half g_M16h[(size_t)512 * 512];
__device__ __half g_G16h[(size_t)64 * 512];
__device__ __half g_G16l[(size_t)64 * 512];
__device__ __half g_xT16 [(size_t)BATCH * NTOK * CDIM];   // [b][n][c] fp16 hi
__device__ __half g_xT16l[(size_t)BATCH * NTOK * CDIM];   // fp16 lo
__device__ __half g_W16h[(size_t)512 * 512];
__device__ __half g_T16h[(size_t)BATCH * NTOK * 512];     // T^T fp16
__device__ float  g_logit[(size_t)BATCH * NTOK * NTOK];
__device__ float  g_P[(size_t)BATCH * 64 * NTOK];
__device__ __half g_v16[(size_t)BATCH * CDIM * NTOK];
__device__ __half g_att16[(size_t)BATCH * NTOK * NTOK];

// ---------------- PTX helpers ----------------------------------------------
__device__ __forceinline__ uint32_t smem_u32(const void* p) {
    uint32_t a;
    asm("{ .reg .u64 t; cvta.to.shared.u64 t, %1; cvt.u32.u64 %0, t; }" : "=r"(a) : "l"(p));
    return a;
}
__device__ __forceinline__ void cpa16(uint32_t dst, const void* src) {
    asm volatile("cp.async.cg.shared.global [%0], [%1], 16;" :: "r"(dst), "l"(src));
}
__device__ __forceinline__ void ldsm4(uint32_t r[4], uint32_t addr) {
    asm volatile("ldmatrix.sync.aligned.m8n8.x4.shared.b16 {%0,%1,%2,%3}, [%4];"
                 : "=r"(r[0]), "=r"(r[1]), "=r"(r[2]), "=r"(r[3]) : "r"(addr));
}
__device__ __forceinline__ void mma16816h(float c[4], const uint32_t a[4], const uint32_t b[2]) {
    asm volatile("mma.sync.aligned.m16n8k16.row.col.f32.f16.f16.f32 "
                 "{%0,%1,%2,%3}, {%4,%5,%6,%7}, {%8,%9}, {%0,%1,%2,%3};"
                 : "+f"(c[0]), "+f"(c[1]), "+f"(c[2]), "+f"(c[3])
                 : "r"(a[0]), "r"(a[1]), "r"(a[2]), "r"(a[3]), "r"(b[0]), "r"(b[1]));
}
__device__ __forceinline__ uint32_t sw_off(int row, int chunk) {
    return (uint32_t)(row * 64 + ((chunk ^ ((row >> 1) & 3)) << 4));
}
__device__ __forceinline__ void split_store_f16(__half* __restrict__ ph, __half* __restrict__ pl,
                                                size_t off, float v0, float v1) {
    __half h0 = __float2half_rn(v0), h1 = __float2half_rn(v1);
    __half l0 = __float2half_rn(v0 - __half2float(h0));
    __half l1 = __float2half_rn(v1 - __half2float(h1));
    __half2 hh; hh.x = h0; hh.y = h1;
    __half2 ll; ll.x = l0; ll.y = l1;
    *reinterpret_cast<__half2*>(ph + off) = hh;
    *reinterpret_cast<__half2*>(pl + off) = ll;
}

#define NSTAGE 3

// ================= P GEMM: 3-term fp16, P[b][r][m] = G[r][:] . x16[m][:] ====
#define P_AH 0
#define P_AM 4096
#define P_BH 8192
#define P_BM 16384
#define P_STAGE 24576
#define SMEM_P (NSTAGE * P_STAGE)

__global__ __launch_bounds__(256, 2) void p_gemm() {
    extern __shared__ __align__(128) char smem[];
    const uint32_t sbase = smem_u32(smem);
    const int tid = threadIdx.x;
    const int wid = tid >> 5, lane = tid & 31;
    const int b = blockIdx.z;
    const int nBase = blockIdx.x * 128;
    const int wm = (wid >> 2) * 32, wn = (wid & 3) * 32;
    const size_t bXT = (size_t)b << 19;

    float acc[2][4][4];
#pragma unroll
    for (int i = 0; i < 2; i++)
#pragma unroll
        for (int j = 0; j < 4; j++)
#pragma unroll
            for (int k = 0; k < 4; k++) acc[i][j][k] = 0.f;

    auto issue_stage = [&](int stage, int kt) {
        const uint32_t sb = sbase + stage * P_STAGE;
        {
            const int row = tid >> 2, ch = tid & 3;
            const uint32_t d = sw_off(row, ch);
            const int s = row * 512 + kt + ch * 8;
            cpa16(sb + P_AH + d, g_G16h + s);
            cpa16(sb + P_AM + d, g_G16l + s);
        }
#pragma unroll
        for (int j = 0; j < 2; j++) {
            const int idx = tid + j * 256;
            const int row = idx >> 2, ch = idx & 3;
            const uint32_t d = sw_off(row, ch);
            const size_t s = bXT + (size_t)(nBase + row) * 512 + kt + ch * 8;
            cpa16(sb + P_BH + d, g_xT16 + s);
            cpa16(sb + P_BM + d, g_xT16l + s);
        }
        asm volatile("cp.async.commit_group;");
    };

    auto compute = [&](int stage) {
        const uint32_t base = sbase + stage * P_STAGE;
        const int sel = lane >> 3;
#pragma unroll
        for (int k8 = 0; k8 < 2; k8++) {
            uint32_t bhf[4][2], bmf[4][2];
#pragma unroll
            for (int pr = 0; pr < 2; pr++) {
                const int nt = 2 * pr + (sel >> 1);
                const int kb = sel & 1;
                const uint32_t ra = base + P_BH + sw_off(wn + nt * 8 + (lane & 7), k8 * 2 + kb);
                uint32_t r[4];
                ldsm4(r, ra);
                bhf[2 * pr][0] = r[0]; bhf[2 * pr][1] = r[1];
                bhf[2 * pr + 1][0] = r[2]; bhf[2 * pr + 1][1] = r[3];
                ldsm4(r, ra + (P_BM - P_BH));
                bmf[2 * pr][0] = r[0]; bmf[2 * pr][1] = r[1];
                bmf[2 * pr + 1][0] = r[2]; bmf[2 * pr + 1][1] = r[3];
            }
#pragma unroll
            for (int mt = 0; mt < 2; mt++) {
                const uint32_t aa = base + P_AH +
                    sw_off(wm + mt * 16 + (sel & 1) * 8 + (lane & 7), k8 * 2 + (sel >> 1));
                uint32_t ah[4], am[4];
                ldsm4(ah, aa);
                ldsm4(am, aa + (P_AM - P_AH));
#pragma unroll
                for (int nt = 0; nt < 4; nt++) mma16816h(acc[mt][nt], ah, bhf[nt]);
#pragma unroll
                for (int nt = 0; nt < 4; nt++) mma16816h(acc[mt][nt], ah, bmf[nt]);
#pragma unroll
                for (int nt = 0; nt < 4; nt++) mma16816h(acc[mt][nt], am, bhf[nt]);
            }
        }
    };

    issue_stage(0, 0);
    issue_stage(1, 32);
    for (int it = 0; it < 16; it++) {
        if (it + 2 < 16) asm volatile("cp.async.wait_group 1;");
        else             asm volatile("cp.async.wait_group 0;");
        __syncthreads();
        if (it + 2 < 16) issue_stage((it + 2) % NSTAGE, (it + 2) * 32);
        compute(it % NSTAGE);
    }

    const int lr = lane >> 2, lc = 2 * (lane & 3);
    float* P = g_P + (size_t)b * 64 * 1024;
#pragma unroll
    for (int mt = 0; mt < 2; mt++) {
#pragma unroll
        for (int nt = 0; nt < 4; nt++) {
            const int r0 = wm + mt * 16 + lr;
            const int c0 = nBase + wn + nt * 8 + lc;
            float2 v0; v0.x = acc[mt][nt][0]; v0.y = acc[mt][nt][1];
            float2 v1; v1.x = acc[mt][nt][2]; v1.y = acc[mt][nt][3];
            *reinterpret_cast<float2*>(P + (size_t)r0 * 1024 + c0) = v0;
            *reinterpret_cast<float2*>(P + (size_t)(r0 + 8) * 1024 + c0) = v1;
        }
    }
}

// ======= fp16 single-term GEMM: 128x128 tile, 4 warps =======================
// MODE 0: v[b][c][n]    = W16h[c][:] . x16[n][:]     K=512,  half out (ld 1024)
// MODE 1: out[b][c][n]  = v16[c][:] . att16[n][:]    K=1024, fp32 out
// MODE 2: logit[b][n][m]= x16[n][:] . T16[m][:]      K=512,  fp32 out
// MODE 3: T[b][m][c1]   = x16[m][:] . M16h[c1][:]    K=512,  half out (ld 512)
#define U_A  0
#define U_B  8192
#define U_STAGE 16384
#define SMEM_U (NSTAGE * U_STAGE)

template <int MODE>
__global__ __launch_bounds__(128, 2) void h1_gemm(float* __restrict__ outp) {
    extern __shared__ __align__(128) char smem[];
    const uint32_t sbase = smem_u32(smem);
    const int tid = threadIdx.x;
    const int wid = tid >> 5, lane = tid & 31;
    const int b = blockIdx.z;
    const int nBase = blockIdx.x * 128;
    const int mBase = blockIdx.y * 128;
    const int wm = (wid >> 1) * 64, wn = (wid & 1) * 64;
    const size_t bQK = (size_t)b << 20;
    const size_t bXT = (size_t)b << 19;

    constexpr int NIT = (MODE == 1) ? 32 : 16;
    constexpr int LD  = (MODE == 1) ? 1024 : 512;

    float acc[4][8][4];
#pragma unroll
    for (int i = 0; i < 4; i++)
#pragma unroll
        for (int j = 0; j < 8; j++)
#pragma unroll
            for (int k = 0; k < 4; k++) acc[i][j][k] = 0.f;

    auto issue_stage = [&](int stage, int kt) {
        const __half *pa, *pb;
        if (MODE == 0) {
            pa = g_W16h + (size_t)mBase * 512 + kt;
            pb = g_xT16 + bXT + (size_t)nBase * 512 + kt;
        } else if (MODE == 1) {
            pa = g_v16 + bXT + (size_t)mBase * 1024 + kt;
            pb = g_att16 + bQK + (size_t)nBase * 1024 + kt;
        } else if (MODE == 2) {
            pa = g_xT16 + bXT + (size_t)mBase * 512 + kt;
            pb = g_T16h + bXT + (size_t)nBase * 512 + kt;
        } else {
            pa = g_xT16 + bXT + (size_t)mBase * 512 + kt;
            pb = g_M16h + (size_t)nBase * 512 + kt;
        }
        const uint32_t sb = sbase + stage * U_STAGE;
#pragma unroll
        for (int j = 0; j < 4; j++) {
            const int idx = tid + j * 128;
            const int row = idx >> 2, ch = idx & 3;
            const uint32_t d = sw_off(row, ch);
            const int s = row * LD + ch * 8;
            cpa16(sb + U_A + d, pa + s);
            cpa16(sb + U_B + d, pb + s);
        }
        asm volatile("cp.async.commit_group;");
    };

    auto compute = [&](int stage) {
        const uint32_t base = sbase + stage * U_STAGE;
        const int sel = lane >> 3;
#pragma unroll
        for (int k8 = 0; k8 < 2; k8++) {
            uint32_t bff[8][2];
#pragma unroll
            for (int pr = 0; pr < 4; pr++) {
                const int nt = 2 * pr + (sel >> 1);
                const int kb = sel & 1;
                uint32_t r[4];
                ldsm4(r, base + U_B + sw_off(wn + nt * 8 + (lane & 7), k8 * 2 + kb));
                bff[2 * pr][0] = r[0]; bff[2 * pr][1] = r[1];
                bff[2 * pr + 1][0] = r[2]; bff[2 * pr + 1][1] = r[3];
            }
#pragma unroll
            for (int mt = 0; mt < 4; mt++) {
                const uint32_t aa = base + U_A +
                    sw_off(wm + mt * 16 + (sel & 1) * 8 + (lane & 7), k8 * 2 + (sel >> 1));
                uint32_t ah[4];
                ldsm4(ah, aa);
#pragma unroll
                for (int nt = 0; nt < 8; nt++) mma16816h(acc[mt][nt], ah, bff[nt]);
            }
        }
    };

    issue_stage(0, 0);
    issue_stage(1, 32);
    for (int it = 0; it < NIT; it++) {
        if (it + 2 < NIT) asm volatile("cp.async.wait_group 1;");
        else              asm volatile("cp.async.wait_group 0;");
        __syncthreads();
        if (it + 2 < NIT) issue_stage((it + 2) % NSTAGE, (it + 2) * 32);
        compute(it % NSTAGE);
    }

    const int lr = lane >> 2, lc = 2 * (lane & 3);
#pragma unroll
    for (int mt = 0; mt < 4; mt++) {
#pragma unroll
        for (int nt = 0; nt < 8; nt++) {
            const int r0 = mBase + wm + mt * 16 + lr;
            const int c0 = nBase + wn + nt * 8 + lc;
            if (MODE == 0 || MODE == 3) {
                __half* ov = (MODE == 0) ? (g_v16 + bXT) : (g_T16h + bXT);
                const int ldo = (MODE == 0) ? 1024 : 512;
                __half2 h0; h0.x = __float2half_rn(acc[mt][nt][0]); h0.y = __float2half_rn(acc[mt][nt][1]);
                __half2 h1; h1.x = __float2half_rn(acc[mt][nt][2]); h1.y = __float2half_rn(acc[mt][nt][3]);
                *reinterpret_cast<__half2*>(ov + (size_t)r0 * ldo + c0) = h0;
                *reinterpret_cast<__half2*>(ov + (size_t)(r0 + 8) * ldo + c0) = h1;
            } else {
                float* of = (MODE == 1) ? (outp + bXT) : (g_logit + bQK);
                float2 v0; v0.x = acc[mt][nt][0]; v0.y = acc[mt][nt][1];
                float2 v1; v1.x = acc[mt][nt][2]; v1.y = acc[mt][nt][3];
                *reinterpret_cast<float2*>(of + (size_t)r0 * 1024 + c0) = v0;
                *reinterpret_cast<float2*>(of + (size_t)(r0 + 8) * 1024 + c0) = v1;
            }
        }
    }
}

// ---------------- small fp32 GEMM for M and G precompute (fp16 out) ---------
template <int IS_G>
__global__ __launch_bounds__(256) void sgemm_split() {
    const float* A = IS_G ? g_rhw : g_WT;
    const int lda = IS_G ? 512 : 1536;
    const float* B = IS_G ? g_WT : (g_WT + 512);
    const int ldb = 1536;

    __shared__ float As[16][72];
    __shared__ float Bs[16][72];
    const int tid = threadIdx.x;
    const int tx = tid & 15, ty = tid >> 4;
    const int rBase = blockIdx.y * 64, cBase = blockIdx.x * 64;

    float acc[4][4];
#pragma unroll
    for (int i = 0; i < 4; i++)
#pragma unroll
        for (int j = 0; j < 4; j++) acc[i][j] = 0.f;

    for (int kt = 0; kt < 512; kt += 16) {
        const int row = tid >> 2, q = (tid & 3) * 4;
        float4 va = *(const float4*)&A[(size_t)(rBase + row) * lda + kt + q];
        As[q + 0][row] = va.x; As[q + 1][row] = va.y;
        As[q + 2][row] = va.z; As[q + 3][row] = va.w;
        float4 vb = *(const float4*)&B[(size_t)(cBase + row) * ldb + kt + q];
        Bs[q + 0][row] = vb.x; Bs[q + 1][row] = vb.y;
        Bs[q + 2][row] = vb.z; Bs[q + 3][row] = vb.w;
        __syncthreads();
#pragma unroll
        for (int k = 0; k < 16; k++) {
            float a[4], bb[4];
            *(float4*)&a[0]  = *(const float4*)&As[k][ty * 4];
            *(float4*)&bb[0] = *(const float4*)&Bs[k][tx * 4];
#pragma unroll
            for (int i = 0; i < 4; i++)
#pragma unroll
                for (int j = 0; j < 4; j++) acc[i][j] += a[i] * bb[j];
        }
        __syncthreads();
    }
#pragma unroll
    for (int i = 0; i < 4; i++) {
        const int row = rBase + ty * 4 + i;
        const int col = cBase + tx * 4;
        if (IS_G) {
            split_store_f16(g_G16h, g_G16l, (size_t)row * 512 + col, acc[i][0], acc[i][1]);
            split_store_f16(g_G16h, g_G16l, (size_t)row * 512 + col + 2, acc[i][2], acc[i][3]);
        } else {
            __half2 h0; h0.x = __float2half_rn(acc[i][0]); h0.y = __float2half_rn(acc[i][1]);
            __half2 h1; h1.x = __float2half_rn(acc[i][2]); h1.y = __float2half_rn(acc[i][3]);
            *reinterpret_cast<__half2*>(g_M16h + (size_t)row * 512 + col) = h0;
            *reinterpret_cast<__half2*>(g_M16h + (size_t)row * 512 + col + 2) = h1;
        }
    }
}

// ---------------- prep kernels ----------------------------------------------
__global__ void transpose_w(const float* __restrict__ W) {
    __shared__ float t[32][33];
    int o0 = blockIdx.x * 32, c0 = blockIdx.y * 32;
    int tx = threadIdx.x, ty = threadIdx.y;
#pragma unroll
    for (int j = 0; j < 32; j += 8)
        t[ty + j][tx] = W[(size_t)(o0 + ty + j) * 512 + c0 + tx];
    __syncthreads();
#pragma unroll
    for (int j = 0; j < 32; j += 8)
        g_WT[(size_t)(c0 + ty + j) * 1536 + o0 + tx] = t[tx][ty + j];
}

__global__ void prep_rhw(const float* __restrict__ rel_h, const float* __restrict__ rel_w) {
    int idx = blockIdx.x * blockDim.x + threadIdx.x;
    if (idx >= 64 * 512) return;
    int r = idx >> 9, c = idx & 511;
    g_rhw[idx] = (r < 32) ? rel_h[c * 32 + r] : rel_w[c * 32 + (r - 32)];
}

__global__ void prep_w16(const float* __restrict__ W) {
    int idx = blockIdx.x * blockDim.x + threadIdx.x;
    if (idx >= 512 * 512) return;
    int cv = idx >> 9, c = idx & 511;
    g_W16h[idx] = __float2half_rn(W[(size_t)(1024 + cv) * 512 + c]);
}

// transpose + fp16 hi/lo split
__global__ void transpose_x(const float* __restrict__ x) {
    __shared__ float t[64][33];
    int b = blockIdx.z;
    int n0 = blockIdx.x * 32, c0 = blockIdx.y * 64;
    const float* src = x + (size_t)b * CDIM * NTOK;
    size_t dbase = (size_t)b * NTOK * CDIM;
    int tx = threadIdx.x, ty = threadIdx.y;
#pragma unroll
    for (int j = 0; j < 8; j++)
        t[ty + j * 8][tx] = src[(size_t)(c0 + ty + j * 8) * NTOK + n0 + tx];
    __syncthreads();
#pragma unroll
    for (int j = 0; j < 4; j++) {
        int n = ty + j * 8;
        float v0 = t[2 * tx][n], v1 = t[2 * tx + 1][n];
        size_t off = dbase + (size_t)(n0 + n) * CDIM + c0 + 2 * tx;
        split_store_f16(g_xT16, g_xT16l, off, v0, v1);
    }
}

// softmax over m with fused pos-bias; writes fp16 att
__global__ __launch_bounds__(256) void softmax_bias() {
    size_t row = blockIdx.x;
    int b = (int)(row >> 10);
    int n = (int)(row & 1023);
    int h = n >> 5, w = n & 31;
    const float* p  = g_logit + row * NTOK;
    const float* ph = g_P + ((size_t)b * 64 + h) * 1024;
    const float* pw = g_P + ((size_t)b * 64 + 32 + w) * 1024;
    int tid = threadIdx.x;

    float4 v = *(const float4*)&p[tid * 4];
    float4 bh = *(const float4*)&ph[tid * 4];
    float4 bw = *(const float4*)&pw[tid * 4];
    v.x += bh.x + bw.x; v.y += bh.y + bw.y;
    v.z += bh.z + bw.z; v.w += bh.w + bw.w;

    float m = fmaxf(fmaxf(v.x, v.y), fmaxf(v.z, v.w));
#pragma unroll
    for (int o = 16; o; o >>= 1) m = fmaxf(m, __shfl_xor_sync(~0u, m, o));
    __shared__ float red[8];
    if ((tid & 31) == 0) red[tid >> 5] = m;
    __syncthreads();
    float bm = red[0];
#pragma unroll
    for (int i = 1; i < 8; i++) bm = fmaxf(bm, red[i]);
    __syncthreads();

    v.x = __expf(v.x - bm); v.y = __expf(v.y - bm);
    v.z = __expf(v.z - bm); v.w = __expf(v.w - bm);
    float s = v.x + v.y + v.z + v.w;
#pragma unroll
    for (int o = 16; o; o >>= 1) s += __shfl_xor_sync(~0u, s, o);
    if ((tid & 31) == 0) red[tid >> 5] = s;
    __syncthreads();
    float bs = 0.f;
#pragma unroll
    for (int i = 0; i < 8; i++) bs += red[i];
    float inv = 1.0f / bs;

    __half2 a0; a0.x = __float2half_rn(v.x * inv); a0.y = __float2half_rn(v.y * inv);
    __half2 a1; a1.x = __float2half_rn(v.z * inv); a1.y = __float2half_rn(v.w * inv);
    size_t off = row * NTOK + tid * 4;
    *reinterpret_cast<__half2*>(g_att16 + off) = a0;
    *reinterpret_cast<__half2*>(g_att16 + off + 2) = a1;
}

// ---------------------------------------------------------------------------
extern "C" void kernel_launch(void* const* d_in, const int* in_sizes, int n_in,
                              void* d_out, int out_size) {
    const float* x     = (const float*)d_in[0];
    const float* Wmat  = (const float*)d_in[1];
    const float* rel_h = (const float*)d_in[2];
    const float* rel_w = (const float*)d_in[3];
    float* out = (float*)d_out;

    static cudaStream_t s1 = nullptr, s2 = nullptr;
    static cudaEvent_t eF1, eF2, eX, eM, eP, eV;
    if (s1 == nullptr) {
        cudaStreamCreateWithFlags(&s1, cudaStreamNonBlocking);
        cudaStreamCreateWithFlags(&s2, cudaStreamNonBlocking);
        cudaEventCreateWithFlags(&eF1, cudaEventDisableTiming);
        cudaEventCreateWithFlags(&eF2, cudaEventDisableTiming);
        cudaEventCreateWithFlags(&eX,  cudaEventDisableTiming);
        cudaEventCreateWithFlags(&eM,  cudaEventDisableTiming);
        cudaEventCreateWithFlags(&eP,  cudaEventDisableTiming);
        cudaEventCreateWithFlags(&eV,  cudaEventDisableTiming);
        cudaFuncSetAttribute(p_gemm,     cudaFuncAttributeMaxDynamicSharedMemorySize, SMEM_P);
        cudaFuncSetAttribute(h1_gemm<0>, cudaFuncAttributeMaxDynamicSharedMemorySize, SMEM_U);
        cudaFuncSetAttribute(h1_gemm<1>, cudaFuncAttributeMaxDynamicSharedMemorySize, SMEM_U);
        cudaFuncSetAttribute(h1_gemm<2>, cudaFuncAttributeMaxDynamicSharedMemorySize, SMEM_U);
        cudaFuncSetAttribute(h1_gemm<3>, cudaFuncAttributeMaxDynamicSharedMemorySize, SMEM_U);
    }

    // fork side streams
    cudaEventRecord(eF1, 0);
    cudaStreamWaitEvent(s1, eF1, 0);
    cudaEventRecord(eF2, 0);
    cudaStreamWaitEvent(s2, eF2, 0);

    // main: x transpose/split
    transpose_x<<<dim3(32, 8, 64), dim3(32, 8)>>>(x);
    cudaEventRecord(eX, 0);

    // s1: W preps -> M, G, then P (needs xT)
    transpose_w<<<dim3(48, 16), dim3(32, 8), 0, s1>>>(Wmat);
    sgemm_split<0><<<dim3(8, 8), 256, 0, s1>>>();                 // M fp16
    cudaEventRecord(eM, s1);
    prep_rhw<<<(64 * 512 + 255) / 256, 256, 0, s1>>>(rel_h, rel_w);
    sgemm_split<1><<<dim3(8, 1), 256, 0, s1>>>();                 // G fp16 h/l
    cudaStreamWaitEvent(s1, eX, 0);
    p_gemm<<<dim3(8, 1, 64), 256, SMEM_P, s1>>>();                // P
    cudaEventRecord(eP, s1);

    // s2: Wv prep -> v (needs xT16)
    prep_w16<<<(512 * 512 + 255) / 256, 256, 0, s2>>>(Wmat);
    cudaStreamWaitEvent(s2, eX, 0);
    h1_gemm<0><<<dim3(8, 4, 64), 128, SMEM_U, s2>>>(nullptr);     // v fp16
    cudaEventRecord(eV, s2);

    // main: T -> logits (both single-term fp16)
    cudaStreamWaitEvent(0, eM, 0);
    h1_gemm<3><<<dim3(4, 8, 64), 128, SMEM_U>>>(nullptr);         // T fp16
    h1_gemm<2><<<dim3(8, 8, 64), 128, SMEM_U>>>(nullptr);         // logits

    // join P, softmax, join v, out
    cudaStreamWaitEvent(0, eP, 0);
    softmax_bias<<<BATCH * NTOK, 256>>>();
    cudaStreamWaitEvent(0, eV, 0);
    h1_gemm<1><<<dim3(8, 4, 64), 128, SMEM_U>>>(out);
}